// round 13
// baseline (speedup 1.0000x reference)
#include <cuda_runtime.h>
#include <cuda_bf16.h>
#include <math.h>
#include <stdint.h>

#define L_SEQ  4096
#define NB     2
#define BLTOK  8192
#define DM     768
#define DI     1536
#define DS     16
#define DTR    48
#define NLAYER 4

#define NIN_W  (2 * DI * DM)
#define NOUT_W (DM * DI)

#define SCH 64
#define SCL 64

// ---------------- scratch ----------------
__device__ float g_h    [BLTOK * DM];
__device__ float g_res  [BLTOK * DM];
__device__ float g_xz   [2 * DI * BLTOK];   // (channel, token)
__device__ float g_xconv[DI * BLTOK];
__device__ float g_dt   [DTR * BLTOK];
__device__ float g_BcT  [DS * BLTOK];       // (n, token)  <-- new layout
__device__ float g_CcT  [DS * BLTOK];       // (n, token)
__device__ float g_delta[DI * BLTOK];
__device__ float g_y    [DI * BLTOK];       // (channel, token)

__device__ float g_P [NB * SCH * DI * DS];
__device__ float g_Q [NB * SCH * DI * DS];
__device__ float g_S0[NB * SCH * DI * DS];

__device__ __nv_bfloat16 g_WinHi[NLAYER * NIN_W],  g_WinLo[NLAYER * NIN_W];
__device__ __nv_bfloat16 g_WoutHi[NLAYER * NOUT_W], g_WoutLo[NLAYER * NOUT_W];
__device__ __nv_bfloat16 g_hnHi[BLTOK * DM],  g_hnLo[BLTOK * DM];
__device__ __nv_bfloat16 g_yHi[BLTOK * DI],   g_yLo[BLTOK * DI];

// ---------------- helpers ----------------
__device__ __forceinline__ uint32_t smem_u32(const void* p) {
    uint32_t a;
    asm("{ .reg .u64 t; cvta.to.shared.u64 t, %1; cvt.u32.u64 %0, t; }" : "=r"(a) : "l"(p));
    return a;
}
#define LDSM_X4(r0, r1, r2, r3, a) \
    asm volatile("ldmatrix.sync.aligned.m8n8.x4.shared.b16 {%0,%1,%2,%3}, [%4];" \
                 : "=r"(r0), "=r"(r1), "=r"(r2), "=r"(r3) : "r"(a))
#define MMA_BF16(c, a0, a1, a2, a3, b0, b1) \
    asm volatile("mma.sync.aligned.m16n8k16.row.col.f32.bf16.bf16.f32 " \
                 "{%0,%1,%2,%3}, {%4,%5,%6,%7}, {%8,%9}, {%0,%1,%2,%3};" \
                 : "+f"((c)[0]), "+f"((c)[1]), "+f"((c)[2]), "+f"((c)[3]) \
                 : "r"(a0), "r"(a1), "r"(a2), "r"(a3), "r"(b0), "r"(b1))
#define CP_A16(dst, src) \
    asm volatile("cp.async.cg.shared.global [%0], [%1], 16;" :: "r"(dst), "l"(src))
#define CP_COMMIT()  asm volatile("cp.async.commit_group;")
#define CP_WAIT(n)   asm volatile("cp.async.wait_group %0;" :: "n"(n))

// ---------------- mma.sync 3xBF16 GEMM ----------------
#define TILE_B  10240
#define STAGE_B 40960
#define EPI_STRIDE 130
#define MMASMEM 81920

template <int LAYOUT>
__device__ __forceinline__ void mma_gemm_body(
    char* dsm,
    const __nv_bfloat16* __restrict__ Ahi, const __nv_bfloat16* __restrict__ Alo,
    const __nv_bfloat16* __restrict__ Bhi, const __nv_bfloat16* __restrict__ Blo,
    float* __restrict__ C, int K, int ldc) {
    const int tid = threadIdx.x;
    const int wid = tid >> 5;
    const int lane = tid & 31;
    const int bm = blockIdx.y * 128;
    const int bn = blockIdx.x * 128;
    const int wm = (wid >> 2) * 64;
    const int wn = (wid & 3) * 32;

    const uint32_t sb = smem_u32(dsm);

    uint32_t so[2];
    size_t offA[2], offB[2];
#pragma unroll
    for (int j = 0; j < 2; j++) {
        int v = tid + j * 256;
        int row = v >> 2, c = v & 3;
        so[j] = row * 80 + c * 16;
        offA[j] = (size_t)(bm + row) * K + c * 8;
        offB[j] = (size_t)(bn + row) * K + c * 8;
    }

    uint32_t aoff[4], boff[2];
    {
        int g = lane >> 3, r = lane & 7;
#pragma unroll
        for (int mt = 0; mt < 4; mt++) {
            int row = wm + mt * 16 + (g & 1) * 8 + r;
            aoff[mt] = row * 80 + (g >> 1) * 16;
        }
#pragma unroll
        for (int p = 0; p < 2; p++) {
            int row = wn + p * 16 + (g >> 1) * 8 + r;
            boff[p] = row * 80 + (g & 1) * 16;
        }
    }

    const int KT = K >> 5;

    auto issue = [&](int kc, int stg) {
        int k0 = kc << 5;
        uint32_t base = sb + stg * STAGE_B;
#pragma unroll
        for (int j = 0; j < 2; j++) {
            uint32_t d = base + so[j];
            CP_A16(d,              Ahi + offA[j] + k0);
            CP_A16(d + TILE_B,     Alo + offA[j] + k0);
            CP_A16(d + 2 * TILE_B, Bhi + offB[j] + k0);
            CP_A16(d + 3 * TILE_B, Blo + offB[j] + k0);
        }
        CP_COMMIT();
    };

    float acc[4][4][4];
#pragma unroll
    for (int mt = 0; mt < 4; mt++)
#pragma unroll
        for (int nt = 0; nt < 4; nt++)
#pragma unroll
            for (int e = 0; e < 4; e++) acc[mt][nt][e] = 0.f;

    issue(0, 0);
    if (KT > 1) issue(1, 1);

    for (int kc = 0; kc < KT; kc++) {
        if (kc + 1 < KT) CP_WAIT(1); else CP_WAIT(0);
        __syncthreads();
        uint32_t base = sb + (kc & 1) * STAGE_B;
        uint32_t sAh = base, sAl = base + TILE_B, sBh = base + 2 * TILE_B, sBl = base + 3 * TILE_B;
#pragma unroll
        for (int ks = 0; ks < 2; ks++) {
            uint32_t kb = ks * 32;
            uint32_t bh[2][4], bl[2][4];
#pragma unroll
            for (int p = 0; p < 2; p++) {
                LDSM_X4(bh[p][0], bh[p][1], bh[p][2], bh[p][3], sBh + boff[p] + kb);
                LDSM_X4(bl[p][0], bl[p][1], bl[p][2], bl[p][3], sBl + boff[p] + kb);
            }
#pragma unroll
            for (int mt = 0; mt < 4; mt++) {
                uint32_t ah[4], al[4];
                LDSM_X4(ah[0], ah[1], ah[2], ah[3], sAh + aoff[mt] + kb);
                LDSM_X4(al[0], al[1], al[2], al[3], sAl + aoff[mt] + kb);
#pragma unroll
                for (int nt = 0; nt < 4; nt++) {
                    int p = nt >> 1, h = (nt & 1) * 2;
                    MMA_BF16(acc[mt][nt], ah[0], ah[1], ah[2], ah[3], bh[p][h], bh[p][h + 1]);
                    MMA_BF16(acc[mt][nt], ah[0], ah[1], ah[2], ah[3], bl[p][h], bl[p][h + 1]);
                    MMA_BF16(acc[mt][nt], al[0], al[1], al[2], al[3], bh[p][h], bh[p][h + 1]);
                }
            }
        }
        __syncthreads();
        if (kc + 2 < KT) issue(kc + 2, kc & 1);
    }

    float* st = (float*)dsm;
    {
        int mr = lane >> 2;
        int nc = (lane & 3) * 2;
#pragma unroll
        for (int mt = 0; mt < 4; mt++) {
#pragma unroll
            for (int nt = 0; nt < 4; nt++) {
                int m0 = wm + mt * 16 + mr;
                int n0 = wn + nt * 8 + nc;
                *(float2*)(st + m0 * EPI_STRIDE + n0) = make_float2(acc[mt][nt][0], acc[mt][nt][1]);
                *(float2*)(st + (m0 + 8) * EPI_STRIDE + n0) = make_float2(acc[mt][nt][2], acc[mt][nt][3]);
            }
        }
    }
    __syncthreads();
    if (LAYOUT == 0) {
        for (int idx = tid; idx < 16384; idx += 256) {
            int r = idx >> 7, c = idx & 127;
            C[(size_t)(bm + r) * ldc + bn + c] = st[r * EPI_STRIDE + c];
        }
    } else {
        for (int idx = tid; idx < 16384; idx += 256) {
            int n = idx >> 7, m = idx & 127;
            C[(size_t)(bn + n) * ldc + bm + m] = st[m * EPI_STRIDE + n];
        }
    }
}

__global__ void __launch_bounds__(256, 2) mma_gemm_a(
    const __nv_bfloat16* __restrict__ Ahi, const __nv_bfloat16* __restrict__ Alo,
    const __nv_bfloat16* __restrict__ Bhi, const __nv_bfloat16* __restrict__ Blo,
    float* __restrict__ C, int K, int ldc) {
    extern __shared__ char dsm[];
    mma_gemm_body<0>(dsm, Ahi, Alo, Bhi, Blo, C, K, ldc);
}
__global__ void __launch_bounds__(256, 2) mma_gemm_b(
    const __nv_bfloat16* __restrict__ Ahi, const __nv_bfloat16* __restrict__ Alo,
    const __nv_bfloat16* __restrict__ Bhi, const __nv_bfloat16* __restrict__ Blo,
    float* __restrict__ C, int K, int ldc) {
    extern __shared__ char dsm[];
    mma_gemm_body<1>(dsm, Ahi, Alo, Bhi, Blo, C, K, ldc);
}

// ---------------- all-layer weight fp32 -> bf16 hi/lo ----------------
#define CVT_TOTAL (NLAYER * (NIN_W + NOUT_W))
__global__ void cvt_all_kernel(const float* __restrict__ inW, const float* __restrict__ outW) {
    int i = blockIdx.x * 256 + threadIdx.x;
    if (i >= CVT_TOTAL) return;
    float v;
    __nv_bfloat16 *hi, *lo;
    if (i < NLAYER * NIN_W) {
        v = inW[i];
        hi = g_WinHi + i; lo = g_WinLo + i;
    } else {
        int j = i - NLAYER * NIN_W;
        v = outW[j];
        hi = g_WoutHi + j; lo = g_WoutLo + j;
    }
    __nv_bfloat16 h = __float2bfloat16(v);
    *hi = h;
    *lo = __float2bfloat16(v - __bfloat162float(h));
}

// ---------------- transpose (d,tok)->(tok,d) + bf16 hi/lo ----------------
__global__ void tcvt_kernel(const float* __restrict__ src, __nv_bfloat16* __restrict__ hi,
                            __nv_bfloat16* __restrict__ lo) {
    __shared__ float t[32][33];
    int tx = threadIdx.x & 31, ty = threadIdx.x >> 5;
    int tok0 = blockIdx.x * 32, d0 = blockIdx.y * 32;
#pragma unroll
    for (int i = 0; i < 4; i++) {
        int d = d0 + ty + i * 8;
        t[ty + i * 8][tx] = src[(size_t)d * BLTOK + tok0 + tx];
    }
    __syncthreads();
#pragma unroll
    for (int i = 0; i < 4; i++) {
        int tok = tok0 + ty + i * 8;
        float v = t[tx][ty + i * 8];
        __nv_bfloat16 h = __float2bfloat16(v);
        size_t o = (size_t)tok * DI + d0 + tx;
        hi[o] = h;
        lo[o] = __float2bfloat16(v - __bfloat162float(h));
    }
}

// ---------------- embed ----------------
__global__ void embed_kernel(const float* __restrict__ x, const float* __restrict__ W,
                             const float* __restrict__ bias) {
    __shared__ float xs[64];
    int tok = blockIdx.x;
    int b = tok >> 12, l = tok & 4095;
    int tid = threadIdx.x;
    if (tid < 64) xs[tid] = x[(b * 64 + tid) * L_SEQ + l];
    __syncthreads();
    for (int e = tid; e < DM; e += 256) {
        const float* w = W + e * 64;
        float acc = bias[e];
#pragma unroll 16
        for (int i = 0; i < 64; i++) acc = fmaf(w[i], xs[i], acc);
        g_h[tok * DM + e] = acc;
    }
}

// ---------------- fused residual + layernorm ----------------
__global__ void resln_kernel(const float* __restrict__ src, float* __restrict__ res,
                             float* __restrict__ outf, __nv_bfloat16* __restrict__ ohi,
                             __nv_bfloat16* __restrict__ olo,
                             const float* __restrict__ w, const float* __restrict__ b, int add) {
    __shared__ float red1[8], red2[8];
    int base = blockIdx.x * DM;
    int tid = threadIdx.x;
    float v0 = src[base + tid];
    float v1 = src[base + tid + 256];
    float v2 = src[base + tid + 512];
    if (add) {
        v0 += res[base + tid];
        v1 += res[base + tid + 256];
        v2 += res[base + tid + 512];
    }
    res[base + tid]       = v0;
    res[base + tid + 256] = v1;
    res[base + tid + 512] = v2;

    float s = v0 + v1 + v2;
#pragma unroll
    for (int o = 16; o; o >>= 1) s += __shfl_xor_sync(0xffffffffu, s, o);
    if ((tid & 31) == 0) red1[tid >> 5] = s;
    __syncthreads();
    float tot = 0.f;
#pragma unroll
    for (int i = 0; i < 8; i++) tot += red1[i];
    float mean = tot * (1.f / DM);

    float d0 = v0 - mean, d1 = v1 - mean, d2 = v2 - mean;
    float sq = d0 * d0 + d1 * d1 + d2 * d2;
#pragma unroll
    for (int o = 16; o; o >>= 1) sq += __shfl_xor_sync(0xffffffffu, sq, o);
    if ((tid & 31) == 0) red2[tid >> 5] = sq;
    __syncthreads();
    float vt = 0.f;
#pragma unroll
    for (int i = 0; i < 8; i++) vt += red2[i];
    float inv = rsqrtf(vt * (1.f / DM) + 1e-5f);

    float o0 = d0 * inv * w[tid]       + b[tid];
    float o1 = d1 * inv * w[tid + 256] + b[tid + 256];
    float o2 = d2 * inv * w[tid + 512] + b[tid + 512];
    if (outf) {
        outf[base + tid]       = o0;
        outf[base + tid + 256] = o1;
        outf[base + tid + 512] = o2;
    } else {
        __nv_bfloat16 h0 = __float2bfloat16(o0), h1 = __float2bfloat16(o1), h2 = __float2bfloat16(o2);
        ohi[base + tid]       = h0;  olo[base + tid]       = __float2bfloat16(o0 - __bfloat162float(h0));
        ohi[base + tid + 256] = h1;  olo[base + tid + 256] = __float2bfloat16(o1 - __bfloat162float(h1));
        ohi[base + tid + 512] = h2;  olo[base + tid + 512] = __float2bfloat16(o2 - __bfloat162float(h2));
    }
}

// ---------------- SIMT SGEMM (x_proj / dt_proj) ----------------
#define BK 16
#define SPAD 4
enum { EPI_STORE = 0, EPI_SOFTPLUS = 1, EPI_TRANS = 2, EPI_XPROJ = 3 };

template <int BM, int BN, int TM, int TN, bool BNT, int EPI>
__device__ __forceinline__ void sgemm_body(
    const float* __restrict__ A, const float* __restrict__ B, float* __restrict__ C,
    int M, int N, int K, const float* __restrict__ bias,
    float* __restrict__ aux1, float* __restrict__ aux2) {
    constexpr int AE = BM * BK / 256;
    constexpr int BE = BN * BK / 256;
    __shared__ float As[BK][BM + SPAD];
    __shared__ float Bs[BK][BN + SPAD];

    int tid = threadIdx.x;
    int bm = blockIdx.y * BM;
    int bn = blockIdx.x * BN;
    int tx = tid % (BN / TN);
    int ty = tid / (BN / TN);

    float acc[TM][TN];
#pragma unroll
    for (int i = 0; i < TM; i++)
#pragma unroll
        for (int j = 0; j < TN; j++) acc[i][j] = 0.f;

    float pa[AE], pb[BE];
    auto loadA = [&](int k0) {
#pragma unroll
        for (int e = 0; e < AE; e++) {
            int i = tid + e * 256;
            int r = i / BK, kk = i % BK;
            int m = bm + r;
            pa[e] = (m < M) ? A[(long)m * K + k0 + kk] : 0.f;
        }
    };
    auto loadB = [&](int k0) {
#pragma unroll
        for (int e = 0; e < BE; e++) {
            int i = tid + e * 256;
            if (BNT) {
                int r = i / BK, kk = i % BK;
                pb[e] = B[(long)(bn + r) * K + k0 + kk];
            } else {
                int kk = i / BN, c = i % BN;
                pb[e] = B[(long)(k0 + kk) * N + bn + c];
            }
        }
    };
    auto storeAB = [&]() {
#pragma unroll
        for (int e = 0; e < AE; e++) {
            int i = tid + e * 256;
            As[i % BK][i / BK] = pa[e];
        }
#pragma unroll
        for (int e = 0; e < BE; e++) {
            int i = tid + e * 256;
            if (BNT) Bs[i % BK][i / BK] = pb[e];
            else     Bs[i / BN][i % BN] = pb[e];
        }
    };

    int KT = K / BK;
    loadA(0); loadB(0);
    storeAB();
    __syncthreads();

    for (int kt = 0; kt < KT; kt++) {
        if (kt + 1 < KT) { loadA((kt + 1) * BK); loadB((kt + 1) * BK); }
#pragma unroll
        for (int kk = 0; kk < BK; kk++) {
            float a[TM], bf[TN];
#pragma unroll
            for (int i = 0; i < TM; i++) a[i] = As[kk][ty * TM + i];
#pragma unroll
            for (int j = 0; j < TN; j++) bf[j] = Bs[kk][tx * TN + j];
#pragma unroll
            for (int i = 0; i < TM; i++)
#pragma unroll
                for (int j = 0; j < TN; j++) acc[i][j] = fmaf(a[i], bf[j], acc[i][j]);
        }
        __syncthreads();
        if (kt + 1 < KT) {
            storeAB();
            __syncthreads();
        }
    }

#pragma unroll
    for (int i = 0; i < TM; i++) {
        int m = bm + ty * TM + i;
        if (m >= M) continue;
#pragma unroll
        for (int j = 0; j < TN; j++) {
            int n = bn + tx * TN + j;
            float v = acc[i][j];
            if (EPI == EPI_STORE) {
                C[(long)m * N + n] = v;
            } else if (EPI == EPI_SOFTPLUS) {
                v += bias[m];
                C[(long)m * N + n] = (v > 20.f) ? v : __logf(1.f + __expf(v));
            } else if (EPI == EPI_TRANS) {
                C[(long)n * M + m] = v;
            } else { // EPI_XPROJ: all outputs row-major (m-major) now
                if (m < DTR)            C[(long)m * N + n] = v;
                else if (m < DTR + DS)  aux1[(long)(m - DTR) * N + n] = v;
                else                    aux2[(long)(m - DTR - DS) * N + n] = v;
            }
        }
    }
}

__global__ void __launch_bounds__(256, 2) sgemm_xproj(
    const float* __restrict__ A, const float* __restrict__ B, float* __restrict__ C,
    int M, int N, int K, float* __restrict__ aux1, float* __restrict__ aux2) {
    sgemm_body<32, 128, 2, 8, false, EPI_XPROJ>(A, B, C, M, N, K, nullptr, aux1, aux2);
}
__global__ void __launch_bounds__(256, 2) sgemm_dtproj(
    const float* __restrict__ A, const float* __restrict__ B, float* __restrict__ C,
    int M, int N, int K, const float* __restrict__ bias) {
    sgemm_body<128, 128, 8, 8, false, EPI_SOFTPLUS>(A, B, C, M, N, K, bias, nullptr, nullptr);
}

// ---------------- depthwise causal conv1d + bias + SiLU (float4) ----------------
__global__ void conv_silu_kernel(const float* __restrict__ cw, const float* __restrict__ cb) {
    int v = blockIdx.x * 256 + threadIdx.x;
    if (v >= DI * BLTOK / 4) return;
    int d = v >> 11;            // / 2048
    int blv = v & 2047;         // float4 index within channel row
    const float4* xp = (const float4*)(g_xz + (size_t)d * BLTOK) + blv;
    float4 cur = xp[0];
    float4 prev = ((blv & 1023) == 0) ? make_float4(0.f, 0.f, 0.f, 0.f) : xp[-1];
    float w0 = cw[d * 4], w1 = cw[d * 4 + 1], w2 = cw[d * 4 + 2], w3 = cw[d * 4 + 3];
    float bv = cb[d];
    float win[8] = {prev.x, prev.y, prev.z, prev.w, cur.x, cur.y, cur.z, cur.w};
    float4 o;
#pragma unroll
    for (int i = 0; i < 4; i++) {
        float a = bv;
        a = fmaf(w0, win[i + 1], a);
        a = fmaf(w1, win[i + 2], a);
        a = fmaf(w2, win[i + 3], a);
        a = fmaf(w3, win[i + 4], a);
        float sg = 1.f / (1.f + __expf(-a));
        ((float*)&o)[i] = a * sg;
    }
    ((float4*)(g_xconv + (size_t)d * BLTOK))[blv] = o;
}

// ---------------- chunked scan pass A (float4 group loads) ----------------
__global__ void scanA_kernel(const float* __restrict__ A_log) {
    int g = blockIdx.x * (blockDim.x >> 5) + (threadIdx.x >> 5);
    int lane = threadIdx.x & 31;
    int c  = g % SCH;
    int dp = (g / SCH) % (DI / 2);
    int b  = g / (SCH * (DI / 2));
    int half = lane >> 4;
    int n = lane & 15;
    int d = dp * 2 + half;

    float Acoef = -expf(A_log[d * DS + n]);

    size_t tbase = (size_t)b * L_SEQ + c * SCL;
    const float4* dp4 = (const float4*)(g_delta + (size_t)d * BLTOK + tbase);
    const float4* up4 = (const float4*)(g_xconv + (size_t)d * BLTOK + tbase);
    const float4* bp4 = (const float4*)(g_BcT + (size_t)n * BLTOK + tbase);

    float P = 1.f, s = 0.f;
#pragma unroll 4
    for (int tg = 0; tg < SCL / 4; tg++) {
        float4 de4 = dp4[tg], u4 = up4[tg], B4 = bp4[tg];
#define ASTEP(cmp) { float dA = __expf(de4.cmp * Acoef); P *= dA; \
                     s = fmaf(dA, s, de4.cmp * u4.cmp * B4.cmp); }
        ASTEP(x) ASTEP(y) ASTEP(z) ASTEP(w)
#undef ASTEP
    }
    size_t o = (((size_t)b * SCH + c) * DI + d) * DS + n;
    g_P[o] = P;
    g_Q[o] = s;
}

// ---------------- pass B ----------------
__global__ void scanB_kernel() {
    int g = blockIdx.x * (blockDim.x >> 5) + (threadIdx.x >> 5);
    int lane = threadIdx.x & 31;
    int dp = g % (DI / 2);
    int b  = g / (DI / 2);
    int half = lane >> 4;
    int n = lane & 15;
    int d = dp * 2 + half;

    float s = 0.f;
    size_t stride = (size_t)DI * DS;
    size_t o = (((size_t)b * SCH) * DI + d) * DS + n;
#pragma unroll 4
    for (int c = 0; c < SCH; c++) {
        g_S0[o] = s;
        s = fmaf(g_P[o], s, g_Q[o]);
        o += stride;
    }
}

// ---------------- pass C (float4 group loads, float4 y store) ----------------
__global__ void scanC_kernel(const float* __restrict__ A_log, const float* __restrict__ Dvec) {
    int g = blockIdx.x * (blockDim.x >> 5) + (threadIdx.x >> 5);
    int lane = threadIdx.x & 31;
    int c  = g % SCH;
    int dp = (g / SCH) % (DI / 2);
    int b  = g / (SCH * (DI / 2));
    int half = lane >> 4;
    int n = lane & 15;
    int d = dp * 2 + half;

    float Acoef = -expf(A_log[d * DS + n]);
    float Dv = Dvec[d];

    size_t tbase = (size_t)b * L_SEQ + c * SCL;
    const float4* dp4 = (const float4*)(g_delta + (size_t)d * BLTOK + tbase);
    const float4* up4 = (const float4*)(g_xconv + (size_t)d * BLTOK + tbase);
    const float4* zp4 = (const float4*)(g_xz + (size_t)(DI + d) * BLTOK + tbase);
    const float4* bp4 = (const float4*)(g_BcT + (size_t)n * BLTOK + tbase);
    const float4* cp4 = (const float4*)(g_CcT + (size_t)n * BLTOK + tbase);
    float4* yp4 = (float4*)(g_y + (size_t)d * BLTOK + tbase);

    float s = g_S0[(((size_t)b * SCH + c) * DI + d) * DS + n];
#pragma unroll 2
    for (int tg = 0; tg < SCL / 4; tg++) {
        float4 de4 = dp4[tg], u4 = up4[tg], B4 = bp4[tg], C4 = cp4[tg], z4 = zp4[tg];
        float4 y4;
#define CSTEP(cmp) { float dA = __expf(de4.cmp * Acoef); \
                     s = fmaf(dA, s, de4.cmp * u4.cmp * B4.cmp); \
                     float p = s * C4.cmp; \
                     p += __shfl_xor_sync(0xffffffffu, p, 8, 16); \
                     p += __shfl_xor_sync(0xffffffffu, p, 4, 16); \
                     p += __shfl_xor_sync(0xffffffffu, p, 2, 16); \
                     p += __shfl_xor_sync(0xffffffffu, p, 1, 16); \
                     float yv = fmaf(Dv, u4.cmp, p); \
                     float sg = 1.f / (1.f + __expf(-z4.cmp)); \
                     y4.cmp = yv * z4.cmp * sg; }
        CSTEP(x) CSTEP(y) CSTEP(z) CSTEP(w)
#undef CSTEP
        if (n == 0) yp4[tg] = y4;
    }
}

// ---------------- host launcher ----------------
extern "C" void kernel_launch(void* const* d_in, const int* in_sizes, int n_in,
                              void* d_out, int out_size) {
    const float* x     = (const float*)d_in[0];
    const float* embW  = (const float*)d_in[1];
    const float* embB  = (const float*)d_in[2];
    const float* normw = (const float*)d_in[3];
    const float* normb = (const float*)d_in[4];
    const float* inW   = (const float*)d_in[5];
    const float* convw = (const float*)d_in[6];
    const float* convb = (const float*)d_in[7];
    const float* xpW   = (const float*)d_in[8];
    const float* dtW   = (const float*)d_in[9];
    const float* dtb   = (const float*)d_in[10];
    const float* Alog  = (const float*)d_in[11];
    const float* Dv    = (const float*)d_in[12];
    const float* outW  = (const float*)d_in[13];
    const float* nfw   = (const float*)d_in[14];
    const float* nfb   = (const float*)d_in[15];
    float* out = (float*)d_out;

    float *h, *res, *xz, *xconv, *dt, *BcT, *CcT, *delta, *y;
    __nv_bfloat16 *winh, *winl, *wouth, *woutl, *hnh, *hnl, *yh, *yl;
    cudaGetSymbolAddress((void**)&h,     g_h);
    cudaGetSymbolAddress((void**)&res,   g_res);
    cudaGetSymbolAddress((void**)&xz,    g_xz);
    cudaGetSymbolAddress((void**)&xconv, g_xconv);
    cudaGetSymbolAddress((void**)&dt,    g_dt);
    cudaGetSymbolAddress((void**)&BcT,   g_BcT);
    cudaGetSymbolAddress((void**)&CcT,   g_CcT);
    cudaGetSymbolAddress((void**)&delta, g_delta);
    cudaGetSymbolAddress((void**)&y,     g_y);
    cudaGetSymbolAddress((void**)&winh,  g_WinHi);
    cudaGetSymbolAddress((void**)&winl,  g_WinLo);
    cudaGetSymbolAddress((void**)&wouth, g_WoutHi);
    cudaGetSymbolAddress((void**)&woutl, g_WoutLo);
    cudaGetSymbolAddress((void**)&hnh,   g_hnHi);
    cudaGetSymbolAddress((void**)&hnl,   g_hnLo);
    cudaGetSymbolAddress((void**)&yh,    g_yHi);
    cudaGetSymbolAddress((void**)&yl,    g_yLo);

    cudaFuncSetAttribute(mma_gemm_a, cudaFuncAttributeMaxDynamicSharedMemorySize, MMASMEM);
    cudaFuncSetAttribute(mma_gemm_b, cudaFuncAttributeMaxDynamicSharedMemorySize, MMASMEM);

    const int SCAN_WARPS = NB * (DI / 2) * SCH;
    const int SCANB_WARPS = NB * (DI / 2);

    embed_kernel<<<BLTOK, 256>>>(x, embW, embB);                                   // 0
    cvt_all_kernel<<<(CVT_TOTAL + 255) / 256, 256>>>(inW, outW);                   // 1

    for (int lyr = 0; lyr < NLAYER; lyr++) {
        resln_kernel<<<BLTOK, 256>>>(h, res, nullptr, hnh, hnl,                    // 2
                                     normw + lyr * DM, normb + lyr * DM, lyr > 0 ? 1 : 0);
        mma_gemm_a<<<dim3(64, 24), 256, MMASMEM>>>(                                // 3 <- profiled
            winh + (size_t)lyr * NIN_W, winl + (size_t)lyr * NIN_W, hnh, hnl, xz, DM, BLTOK);
        conv_silu_kernel<<<(DI * BLTOK / 4 + 255) / 256, 256>>>(convw + lyr * DI * 4, convb + lyr * DI);
        sgemm_xproj<<<dim3(64, 3), 256>>>(
            xpW + (long)lyr * (DTR + 2 * DS) * DI, xconv, dt, DTR + 2 * DS, BLTOK, DI, BcT, CcT);
        sgemm_dtproj<<<dim3(64, 12), 256>>>(
            dtW + (long)lyr * DI * DTR, dt, delta, DI, BLTOK, DTR, dtb + lyr * DI);
        scanA_kernel<<<SCAN_WARPS / 4, 128>>>(Alog + (long)lyr * DI * DS);
        scanB_kernel<<<SCANB_WARPS / 4, 128>>>();
        scanC_kernel<<<SCAN_WARPS / 4, 128>>>(Alog + (long)lyr * DI * DS, Dv + lyr * DI);
        tcvt_kernel<<<dim3(BLTOK / 32, DI / 32), 256>>>(y, yh, yl);
        mma_gemm_b<<<dim3(64, 6), 256, MMASMEM>>>(
            wouth + (size_t)lyr * NOUT_W, woutl + (size_t)lyr * NOUT_W, yh, yl, h, DI, DM);
    }

    resln_kernel<<<BLTOK, 256>>>(h, res, out, nullptr, nullptr, nfw, nfb, 1);
}

// round 14
// speedup vs baseline: 1.0968x; 1.0968x over previous
#include <cuda_runtime.h>
#include <cuda_bf16.h>
#include <math.h>
#include <stdint.h>

#define L_SEQ  4096
#define NB     2
#define BLTOK  8192
#define DM     768
#define DI     1536
#define DS     16
#define DTR    48
#define NLAYER 4

#define NIN_W  (2 * DI * DM)
#define NOUT_W (DM * DI)

#define SCH 64
#define SCL 64

// ---------------- scratch ----------------
__device__ float g_h    [BLTOK * DM];
__device__ float g_res  [BLTOK * DM];
__device__ float g_xz   [2 * DI * BLTOK];   // (channel, token)
__device__ float g_xconv[DI * BLTOK];
__device__ float g_dt   [DTR * BLTOK];
__device__ float g_BcT  [BLTOK * DS];       // (token, n)  -- R10 layout (coalesced half-warp reads)
__device__ float g_CcT  [BLTOK * DS];
__device__ float g_delta[DI * BLTOK];
__device__ float g_y    [DI * BLTOK];       // (channel, token)

__device__ float g_P [NB * SCH * DI * DS];
__device__ float g_Q [NB * SCH * DI * DS];
__device__ float g_S0[NB * SCH * DI * DS];

__device__ __nv_bfloat16 g_WinHi[NLAYER * NIN_W],  g_WinLo[NLAYER * NIN_W];
__device__ __nv_bfloat16 g_WoutHi[NLAYER * NOUT_W], g_WoutLo[NLAYER * NOUT_W];
__device__ __nv_bfloat16 g_hnHi[BLTOK * DM],  g_hnLo[BLTOK * DM];
__device__ __nv_bfloat16 g_yHi[BLTOK * DI],   g_yLo[BLTOK * DI];

// ---------------- helpers ----------------
__device__ __forceinline__ uint32_t smem_u32(const void* p) {
    uint32_t a;
    asm("{ .reg .u64 t; cvta.to.shared.u64 t, %1; cvt.u32.u64 %0, t; }" : "=r"(a) : "l"(p));
    return a;
}
#define LDSM_X4(r0, r1, r2, r3, a) \
    asm volatile("ldmatrix.sync.aligned.m8n8.x4.shared.b16 {%0,%1,%2,%3}, [%4];" \
                 : "=r"(r0), "=r"(r1), "=r"(r2), "=r"(r3) : "r"(a))
#define MMA_BF16(c, a0, a1, a2, a3, b0, b1) \
    asm volatile("mma.sync.aligned.m16n8k16.row.col.f32.bf16.bf16.f32 " \
                 "{%0,%1,%2,%3}, {%4,%5,%6,%7}, {%8,%9}, {%0,%1,%2,%3};" \
                 : "+f"((c)[0]), "+f"((c)[1]), "+f"((c)[2]), "+f"((c)[3]) \
                 : "r"(a0), "r"(a1), "r"(a2), "r"(a3), "r"(b0), "r"(b1))
#define CP_A16(dst, src) \
    asm volatile("cp.async.cg.shared.global [%0], [%1], 16;" :: "r"(dst), "l"(src))
#define CP_COMMIT()  asm volatile("cp.async.commit_group;")
#define CP_WAIT(n)   asm volatile("cp.async.wait_group %0;" :: "n"(n))

// ---------------- mma.sync 3xBF16 GEMM ----------------
#define TILE_B  10240
#define STAGE_B 40960
#define EPI_STRIDE 130
#define MMASMEM 81920

template <int LAYOUT>
__device__ __forceinline__ void mma_gemm_body(
    char* dsm,
    const __nv_bfloat16* __restrict__ Ahi, const __nv_bfloat16* __restrict__ Alo,
    const __nv_bfloat16* __restrict__ Bhi, const __nv_bfloat16* __restrict__ Blo,
    float* __restrict__ C, int K, int ldc) {
    const int tid = threadIdx.x;
    const int wid = tid >> 5;
    const int lane = tid & 31;
    const int bm = blockIdx.y * 128;
    const int bn = blockIdx.x * 128;
    const int wm = (wid >> 2) * 64;
    const int wn = (wid & 3) * 32;

    const uint32_t sb = smem_u32(dsm);

    uint32_t so[2];
    size_t offA[2], offB[2];
#pragma unroll
    for (int j = 0; j < 2; j++) {
        int v = tid + j * 256;
        int row = v >> 2, c = v & 3;
        so[j] = row * 80 + c * 16;
        offA[j] = (size_t)(bm + row) * K + c * 8;
        offB[j] = (size_t)(bn + row) * K + c * 8;
    }

    uint32_t aoff[4], boff[2];
    {
        int g = lane >> 3, r = lane & 7;
#pragma unroll
        for (int mt = 0; mt < 4; mt++) {
            int row = wm + mt * 16 + (g & 1) * 8 + r;
            aoff[mt] = row * 80 + (g >> 1) * 16;
        }
#pragma unroll
        for (int p = 0; p < 2; p++) {
            int row = wn + p * 16 + (g >> 1) * 8 + r;
            boff[p] = row * 80 + (g & 1) * 16;
        }
    }

    const int KT = K >> 5;

    auto issue = [&](int kc, int stg) {
        int k0 = kc << 5;
        uint32_t base = sb + stg * STAGE_B;
#pragma unroll
        for (int j = 0; j < 2; j++) {
            uint32_t d = base + so[j];
            CP_A16(d,              Ahi + offA[j] + k0);
            CP_A16(d + TILE_B,     Alo + offA[j] + k0);
            CP_A16(d + 2 * TILE_B, Bhi + offB[j] + k0);
            CP_A16(d + 3 * TILE_B, Blo + offB[j] + k0);
        }
        CP_COMMIT();
    };

    float acc[4][4][4];
#pragma unroll
    for (int mt = 0; mt < 4; mt++)
#pragma unroll
        for (int nt = 0; nt < 4; nt++)
#pragma unroll
            for (int e = 0; e < 4; e++) acc[mt][nt][e] = 0.f;

    issue(0, 0);
    if (KT > 1) issue(1, 1);

    for (int kc = 0; kc < KT; kc++) {
        if (kc + 1 < KT) CP_WAIT(1); else CP_WAIT(0);
        __syncthreads();
        uint32_t base = sb + (kc & 1) * STAGE_B;
        uint32_t sAh = base, sAl = base + TILE_B, sBh = base + 2 * TILE_B, sBl = base + 3 * TILE_B;
#pragma unroll
        for (int ks = 0; ks < 2; ks++) {
            uint32_t kb = ks * 32;
            uint32_t bh[2][4], bl[2][4];
#pragma unroll
            for (int p = 0; p < 2; p++) {
                LDSM_X4(bh[p][0], bh[p][1], bh[p][2], bh[p][3], sBh + boff[p] + kb);
                LDSM_X4(bl[p][0], bl[p][1], bl[p][2], bl[p][3], sBl + boff[p] + kb);
            }
#pragma unroll
            for (int mt = 0; mt < 4; mt++) {
                uint32_t ah[4], al[4];
                LDSM_X4(ah[0], ah[1], ah[2], ah[3], sAh + aoff[mt] + kb);
                LDSM_X4(al[0], al[1], al[2], al[3], sAl + aoff[mt] + kb);
#pragma unroll
                for (int nt = 0; nt < 4; nt++) {
                    int p = nt >> 1, h = (nt & 1) * 2;
                    MMA_BF16(acc[mt][nt], ah[0], ah[1], ah[2], ah[3], bh[p][h], bh[p][h + 1]);
                    MMA_BF16(acc[mt][nt], ah[0], ah[1], ah[2], ah[3], bl[p][h], bl[p][h + 1]);
                    MMA_BF16(acc[mt][nt], al[0], al[1], al[2], al[3], bh[p][h], bh[p][h + 1]);
                }
            }
        }
        __syncthreads();
        if (kc + 2 < KT) issue(kc + 2, kc & 1);
    }

    float* st = (float*)dsm;
    {
        int mr = lane >> 2;
        int nc = (lane & 3) * 2;
#pragma unroll
        for (int mt = 0; mt < 4; mt++) {
#pragma unroll
            for (int nt = 0; nt < 4; nt++) {
                int m0 = wm + mt * 16 + mr;
                int n0 = wn + nt * 8 + nc;
                *(float2*)(st + m0 * EPI_STRIDE + n0) = make_float2(acc[mt][nt][0], acc[mt][nt][1]);
                *(float2*)(st + (m0 + 8) * EPI_STRIDE + n0) = make_float2(acc[mt][nt][2], acc[mt][nt][3]);
            }
        }
    }
    __syncthreads();
    if (LAYOUT == 0) {
        for (int idx = tid; idx < 16384; idx += 256) {
            int r = idx >> 7, c = idx & 127;
            C[(size_t)(bm + r) * ldc + bn + c] = st[r * EPI_STRIDE + c];
        }
    } else {
        for (int idx = tid; idx < 16384; idx += 256) {
            int n = idx >> 7, m = idx & 127;
            C[(size_t)(bn + n) * ldc + bm + m] = st[m * EPI_STRIDE + n];
        }
    }
}

__global__ void __launch_bounds__(256, 2) mma_gemm_a(
    const __nv_bfloat16* __restrict__ Ahi, const __nv_bfloat16* __restrict__ Alo,
    const __nv_bfloat16* __restrict__ Bhi, const __nv_bfloat16* __restrict__ Blo,
    float* __restrict__ C, int K, int ldc) {
    extern __shared__ char dsm[];
    mma_gemm_body<0>(dsm, Ahi, Alo, Bhi, Blo, C, K, ldc);
}
__global__ void __launch_bounds__(256, 2) mma_gemm_b(
    const __nv_bfloat16* __restrict__ Ahi, const __nv_bfloat16* __restrict__ Alo,
    const __nv_bfloat16* __restrict__ Bhi, const __nv_bfloat16* __restrict__ Blo,
    float* __restrict__ C, int K, int ldc) {
    extern __shared__ char dsm[];
    mma_gemm_body<1>(dsm, Ahi, Alo, Bhi, Blo, C, K, ldc);
}

// ---------------- all-layer weight fp32 -> bf16 hi/lo ----------------
#define CVT_TOTAL (NLAYER * (NIN_W + NOUT_W))
__global__ void cvt_all_kernel(const float* __restrict__ inW, const float* __restrict__ outW) {
    int i = blockIdx.x * 256 + threadIdx.x;
    if (i >= CVT_TOTAL) return;
    float v;
    __nv_bfloat16 *hi, *lo;
    if (i < NLAYER * NIN_W) {
        v = inW[i];
        hi = g_WinHi + i; lo = g_WinLo + i;
    } else {
        int j = i - NLAYER * NIN_W;
        v = outW[j];
        hi = g_WoutHi + j; lo = g_WoutLo + j;
    }
    __nv_bfloat16 h = __float2bfloat16(v);
    *hi = h;
    *lo = __float2bfloat16(v - __bfloat162float(h));
}

// ---------------- transpose (d,tok)->(tok,d) + bf16 hi/lo ----------------
__global__ void tcvt_kernel(const float* __restrict__ src, __nv_bfloat16* __restrict__ hi,
                            __nv_bfloat16* __restrict__ lo) {
    __shared__ float t[32][33];
    int tx = threadIdx.x & 31, ty = threadIdx.x >> 5;
    int tok0 = blockIdx.x * 32, d0 = blockIdx.y * 32;
#pragma unroll
    for (int i = 0; i < 4; i++) {
        int d = d0 + ty + i * 8;
        t[ty + i * 8][tx] = src[(size_t)d * BLTOK + tok0 + tx];
    }
    __syncthreads();
#pragma unroll
    for (int i = 0; i < 4; i++) {
        int tok = tok0 + ty + i * 8;
        float v = t[tx][ty + i * 8];
        __nv_bfloat16 h = __float2bfloat16(v);
        size_t o = (size_t)tok * DI + d0 + tx;
        hi[o] = h;
        lo[o] = __float2bfloat16(v - __bfloat162float(h));
    }
}

// ---------------- embed ----------------
__global__ void embed_kernel(const float* __restrict__ x, const float* __restrict__ W,
                             const float* __restrict__ bias) {
    __shared__ float xs[64];
    int tok = blockIdx.x;
    int b = tok >> 12, l = tok & 4095;
    int tid = threadIdx.x;
    if (tid < 64) xs[tid] = x[(b * 64 + tid) * L_SEQ + l];
    __syncthreads();
    for (int e = tid; e < DM; e += 256) {
        const float* w = W + e * 64;
        float acc = bias[e];
#pragma unroll 16
        for (int i = 0; i < 64; i++) acc = fmaf(w[i], xs[i], acc);
        g_h[tok * DM + e] = acc;
    }
}

// ---------------- fused residual + layernorm ----------------
__global__ void resln_kernel(const float* __restrict__ src, float* __restrict__ res,
                             float* __restrict__ outf, __nv_bfloat16* __restrict__ ohi,
                             __nv_bfloat16* __restrict__ olo,
                             const float* __restrict__ w, const float* __restrict__ b, int add) {
    __shared__ float red1[8], red2[8];
    int base = blockIdx.x * DM;
    int tid = threadIdx.x;
    float v0 = src[base + tid];
    float v1 = src[base + tid + 256];
    float v2 = src[base + tid + 512];
    if (add) {
        v0 += res[base + tid];
        v1 += res[base + tid + 256];
        v2 += res[base + tid + 512];
    }
    res[base + tid]       = v0;
    res[base + tid + 256] = v1;
    res[base + tid + 512] = v2;

    float s = v0 + v1 + v2;
#pragma unroll
    for (int o = 16; o; o >>= 1) s += __shfl_xor_sync(0xffffffffu, s, o);
    if ((tid & 31) == 0) red1[tid >> 5] = s;
    __syncthreads();
    float tot = 0.f;
#pragma unroll
    for (int i = 0; i < 8; i++) tot += red1[i];
    float mean = tot * (1.f / DM);

    float d0 = v0 - mean, d1 = v1 - mean, d2 = v2 - mean;
    float sq = d0 * d0 + d1 * d1 + d2 * d2;
#pragma unroll
    for (int o = 16; o; o >>= 1) sq += __shfl_xor_sync(0xffffffffu, sq, o);
    if ((tid & 31) == 0) red2[tid >> 5] = sq;
    __syncthreads();
    float vt = 0.f;
#pragma unroll
    for (int i = 0; i < 8; i++) vt += red2[i];
    float inv = rsqrtf(vt * (1.f / DM) + 1e-5f);

    float o0 = d0 * inv * w[tid]       + b[tid];
    float o1 = d1 * inv * w[tid + 256] + b[tid + 256];
    float o2 = d2 * inv * w[tid + 512] + b[tid + 512];
    if (outf) {
        outf[base + tid]       = o0;
        outf[base + tid + 256] = o1;
        outf[base + tid + 512] = o2;
    } else {
        __nv_bfloat16 h0 = __float2bfloat16(o0), h1 = __float2bfloat16(o1), h2 = __float2bfloat16(o2);
        ohi[base + tid]       = h0;  olo[base + tid]       = __float2bfloat16(o0 - __bfloat162float(h0));
        ohi[base + tid + 256] = h1;  olo[base + tid + 256] = __float2bfloat16(o1 - __bfloat162float(h1));
        ohi[base + tid + 512] = h2;  olo[base + tid + 512] = __float2bfloat16(o2 - __bfloat162float(h2));
    }
}

// ---------------- SIMT SGEMM (x_proj / dt_proj) ----------------
#define BK 16
#define SPAD 4
enum { EPI_STORE = 0, EPI_SOFTPLUS = 1, EPI_TRANS = 2, EPI_XPROJ = 3 };

template <int BM, int BN, int TM, int TN, bool BNT, int EPI>
__device__ __forceinline__ void sgemm_body(
    const float* __restrict__ A, const float* __restrict__ B, float* __restrict__ C,
    int M, int N, int K, const float* __restrict__ bias,
    float* __restrict__ aux1, float* __restrict__ aux2) {
    constexpr int AE = BM * BK / 256;
    constexpr int BE = BN * BK / 256;
    __shared__ float As[BK][BM + SPAD];
    __shared__ float Bs[BK][BN + SPAD];

    int tid = threadIdx.x;
    int bm = blockIdx.y * BM;
    int bn = blockIdx.x * BN;
    int tx = tid % (BN / TN);
    int ty = tid / (BN / TN);

    float acc[TM][TN];
#pragma unroll
    for (int i = 0; i < TM; i++)
#pragma unroll
        for (int j = 0; j < TN; j++) acc[i][j] = 0.f;

    float pa[AE], pb[BE];
    auto loadA = [&](int k0) {
#pragma unroll
        for (int e = 0; e < AE; e++) {
            int i = tid + e * 256;
            int r = i / BK, kk = i % BK;
            int m = bm + r;
            pa[e] = (m < M) ? A[(long)m * K + k0 + kk] : 0.f;
        }
    };
    auto loadB = [&](int k0) {
#pragma unroll
        for (int e = 0; e < BE; e++) {
            int i = tid + e * 256;
            if (BNT) {
                int r = i / BK, kk = i % BK;
                pb[e] = B[(long)(bn + r) * K + k0 + kk];
            } else {
                int kk = i / BN, c = i % BN;
                pb[e] = B[(long)(k0 + kk) * N + bn + c];
            }
        }
    };
    auto storeAB = [&]() {
#pragma unroll
        for (int e = 0; e < AE; e++) {
            int i = tid + e * 256;
            As[i % BK][i / BK] = pa[e];
        }
#pragma unroll
        for (int e = 0; e < BE; e++) {
            int i = tid + e * 256;
            if (BNT) Bs[i % BK][i / BK] = pb[e];
            else     Bs[i / BN][i % BN] = pb[e];
        }
    };

    int KT = K / BK;
    loadA(0); loadB(0);
    storeAB();
    __syncthreads();

    for (int kt = 0; kt < KT; kt++) {
        if (kt + 1 < KT) { loadA((kt + 1) * BK); loadB((kt + 1) * BK); }
#pragma unroll
        for (int kk = 0; kk < BK; kk++) {
            float a[TM], bf[TN];
#pragma unroll
            for (int i = 0; i < TM; i++) a[i] = As[kk][ty * TM + i];
#pragma unroll
            for (int j = 0; j < TN; j++) bf[j] = Bs[kk][tx * TN + j];
#pragma unroll
            for (int i = 0; i < TM; i++)
#pragma unroll
                for (int j = 0; j < TN; j++) acc[i][j] = fmaf(a[i], bf[j], acc[i][j]);
        }
        __syncthreads();
        if (kt + 1 < KT) {
            storeAB();
            __syncthreads();
        }
    }

#pragma unroll
    for (int i = 0; i < TM; i++) {
        int m = bm + ty * TM + i;
        if (m >= M) continue;
#pragma unroll
        for (int j = 0; j < TN; j++) {
            int n = bn + tx * TN + j;
            float v = acc[i][j];
            if (EPI == EPI_STORE) {
                C[(long)m * N + n] = v;
            } else if (EPI == EPI_SOFTPLUS) {
                v += bias[m];
                C[(long)m * N + n] = (v > 20.f) ? v : __logf(1.f + __expf(v));
            } else if (EPI == EPI_TRANS) {
                C[(long)n * M + m] = v;
            } else { // EPI_XPROJ: Bc/Cc stored (token, n)
                if (m < DTR)            C[(long)m * N + n] = v;
                else if (m < DTR + DS)  aux1[(long)n * DS + (m - DTR)] = v;
                else                    aux2[(long)n * DS + (m - DTR - DS)] = v;
            }
        }
    }
}

__global__ void __launch_bounds__(256, 2) sgemm_xproj(
    const float* __restrict__ A, const float* __restrict__ B, float* __restrict__ C,
    int M, int N, int K, float* __restrict__ aux1, float* __restrict__ aux2) {
    sgemm_body<32, 128, 2, 8, false, EPI_XPROJ>(A, B, C, M, N, K, nullptr, aux1, aux2);
}
__global__ void __launch_bounds__(256, 2) sgemm_dtproj(
    const float* __restrict__ A, const float* __restrict__ B, float* __restrict__ C,
    int M, int N, int K, const float* __restrict__ bias) {
    sgemm_body<128, 128, 8, 8, false, EPI_SOFTPLUS>(A, B, C, M, N, K, bias, nullptr, nullptr);
}

// ---------------- depthwise causal conv1d + bias + SiLU (R10 scalar) ----------------
__global__ void conv_silu_kernel(const float* __restrict__ cw, const float* __restrict__ cb) {
    int idx = blockIdx.x * 256 + threadIdx.x;
    if (idx >= DI * BLTOK) return;
    int d = idx >> 13;
    int bl = idx & 8191;
    int l = bl & 4095;
    const float* xp = g_xz + (long)d * BLTOK + bl;
    float w0 = cw[d * 4], w1 = cw[d * 4 + 1], w2 = cw[d * 4 + 2], w3 = cw[d * 4 + 3];
    float acc = cb[d];
    if (l >= 3) acc = fmaf(w0, xp[-3], acc);
    if (l >= 2) acc = fmaf(w1, xp[-2], acc);
    if (l >= 1) acc = fmaf(w2, xp[-1], acc);
    acc = fmaf(w3, xp[0], acc);
    float sg = 1.f / (1.f + __expf(-acc));
    g_xconv[idx] = acc * sg;
}

// ---------------- chunked scan pass A (R10 scalar loads) ----------------
__global__ void scanA_kernel(const float* __restrict__ A_log) {
    int g = blockIdx.x * (blockDim.x >> 5) + (threadIdx.x >> 5);
    int lane = threadIdx.x & 31;
    int c  = g % SCH;
    int dp = (g / SCH) % (DI / 2);
    int b  = g / (SCH * (DI / 2));
    int half = lane >> 4;
    int n = lane & 15;
    int d = dp * 2 + half;

    float Acoef = -expf(A_log[d * DS + n]);

    const float* dptr = g_delta + (size_t)d * BLTOK + b * L_SEQ + c * SCL;
    const float* uptr = g_xconv + (size_t)d * BLTOK + b * L_SEQ + c * SCL;
    const float* bptr = g_BcT + (size_t)(b * L_SEQ + c * SCL) * DS + n;

    float P = 1.f, s = 0.f;
#pragma unroll 8
    for (int t = 0; t < SCL; t++) {
        float de = dptr[t];
        float u  = uptr[t];
        float Bn = bptr[(size_t)t * DS];
        float dA = __expf(de * Acoef);
        P *= dA;
        s = fmaf(dA, s, de * u * Bn);
    }
    size_t o = (((size_t)b * SCH + c) * DI + d) * DS + n;
    g_P[o] = P;
    g_Q[o] = s;
}

// ---------------- pass B ----------------
__global__ void scanB_kernel() {
    int g = blockIdx.x * (blockDim.x >> 5) + (threadIdx.x >> 5);
    int lane = threadIdx.x & 31;
    int dp = g % (DI / 2);
    int b  = g / (DI / 2);
    int half = lane >> 4;
    int n = lane & 15;
    int d = dp * 2 + half;

    float s = 0.f;
    size_t stride = (size_t)DI * DS;
    size_t o = (((size_t)b * SCH) * DI + d) * DS + n;
#pragma unroll 4
    for (int c = 0; c < SCH; c++) {
        g_S0[o] = s;
        s = fmaf(g_P[o], s, g_Q[o]);
        o += stride;
    }
}

// ---------------- pass C (R10: unconditional silu, predicated store) ----------------
__global__ void scanC_kernel(const float* __restrict__ A_log, const float* __restrict__ Dvec) {
    int g = blockIdx.x * (blockDim.x >> 5) + (threadIdx.x >> 5);
    int lane = threadIdx.x & 31;
    int c  = g % SCH;
    int dp = (g / SCH) % (DI / 2);
    int b  = g / (SCH * (DI / 2));
    int half = lane >> 4;
    int n = lane & 15;
    int d = dp * 2 + half;

    float Acoef = -expf(A_log[d * DS + n]);
    float Dv = Dvec[d];

    const float* dptr = g_delta + (size_t)d * BLTOK + b * L_SEQ + c * SCL;
    const float* uptr = g_xconv + (size_t)d * BLTOK + b * L_SEQ + c * SCL;
    const float* zptr = g_xz + (size_t)(DI + d) * BLTOK + b * L_SEQ + c * SCL;
    const float* bptr = g_BcT + (size_t)(b * L_SEQ + c * SCL) * DS + n;
    const float* cptr = g_CcT + (size_t)(b * L_SEQ + c * SCL) * DS + n;
    float* yptr = g_y + (size_t)d * BLTOK + b * L_SEQ + c * SCL;

    float s = g_S0[(((size_t)b * SCH + c) * DI + d) * DS + n];
#pragma unroll 4
    for (int t = 0; t < SCL; t++) {
        float de = dptr[t];
        float u  = uptr[t];
        float zv = zptr[t];
        float Bn = bptr[(size_t)t * DS];
        float Cn = cptr[(size_t)t * DS];
        float dA = __expf(de * Acoef);
        s = fmaf(dA, s, de * u * Bn);
        float p = s * Cn;
        p += __shfl_xor_sync(0xffffffffu, p, 8, 16);
        p += __shfl_xor_sync(0xffffffffu, p, 4, 16);
        p += __shfl_xor_sync(0xffffffffu, p, 2, 16);
        p += __shfl_xor_sync(0xffffffffu, p, 1, 16);
        float yv = fmaf(Dv, u, p);
        float sg = 1.f / (1.f + __expf(-zv));
        yv *= zv * sg;
        if (n == 0) yptr[t] = yv;
    }
}

// ---------------- host launcher ----------------
extern "C" void kernel_launch(void* const* d_in, const int* in_sizes, int n_in,
                              void* d_out, int out_size) {
    const float* x     = (const float*)d_in[0];
    const float* embW  = (const float*)d_in[1];
    const float* embB  = (const float*)d_in[2];
    const float* normw = (const float*)d_in[3];
    const float* normb = (const float*)d_in[4];
    const float* inW   = (const float*)d_in[5];
    const float* convw = (const float*)d_in[6];
    const float* convb = (const float*)d_in[7];
    const float* xpW   = (const float*)d_in[8];
    const float* dtW   = (const float*)d_in[9];
    const float* dtb   = (const float*)d_in[10];
    const float* Alog  = (const float*)d_in[11];
    const float* Dv    = (const float*)d_in[12];
    const float* outW  = (const float*)d_in[13];
    const float* nfw   = (const float*)d_in[14];
    const float* nfb   = (const float*)d_in[15];
    float* out = (float*)d_out;

    float *h, *res, *xz, *xconv, *dt, *BcT, *CcT, *delta, *y;
    __nv_bfloat16 *winh, *winl, *wouth, *woutl, *hnh, *hnl, *yh, *yl;
    cudaGetSymbolAddress((void**)&h,     g_h);
    cudaGetSymbolAddress((void**)&res,   g_res);
    cudaGetSymbolAddress((void**)&xz,    g_xz);
    cudaGetSymbolAddress((void**)&xconv, g_xconv);
    cudaGetSymbolAddress((void**)&dt,    g_dt);
    cudaGetSymbolAddress((void**)&BcT,   g_BcT);
    cudaGetSymbolAddress((void**)&CcT,   g_CcT);
    cudaGetSymbolAddress((void**)&delta, g_delta);
    cudaGetSymbolAddress((void**)&y,     g_y);
    cudaGetSymbolAddress((void**)&winh,  g_WinHi);
    cudaGetSymbolAddress((void**)&winl,  g_WinLo);
    cudaGetSymbolAddress((void**)&wouth, g_WoutHi);
    cudaGetSymbolAddress((void**)&woutl, g_WoutLo);
    cudaGetSymbolAddress((void**)&hnh,   g_hnHi);
    cudaGetSymbolAddress((void**)&hnl,   g_hnLo);
    cudaGetSymbolAddress((void**)&yh,    g_yHi);
    cudaGetSymbolAddress((void**)&yl,    g_yLo);

    cudaFuncSetAttribute(mma_gemm_a, cudaFuncAttributeMaxDynamicSharedMemorySize, MMASMEM);
    cudaFuncSetAttribute(mma_gemm_b, cudaFuncAttributeMaxDynamicSharedMemorySize, MMASMEM);

    const int SCAN_WARPS = NB * (DI / 2) * SCH;
    const int SCANB_WARPS = NB * (DI / 2);

    embed_kernel<<<BLTOK, 256>>>(x, embW, embB);                                   // 0
    cvt_all_kernel<<<(CVT_TOTAL + 255) / 256, 256>>>(inW, outW);                   // 1

    for (int lyr = 0; lyr < NLAYER; lyr++) {
        resln_kernel<<<BLTOK, 256>>>(h, res, nullptr, hnh, hnl,                    // 2
                                     normw + lyr * DM, normb + lyr * DM, lyr > 0 ? 1 : 0);
        if (lyr == 0) {
            // dummy scanC at capture index 3: reads zero-init/stale scratch, writes g_y
            // (fully overwritten by the real layer-0 scanC before tcvt reads it).
            // Output-invariant; exists solely so ncu profiles scanC this round.
            scanC_kernel<<<SCAN_WARPS / 4, 128>>>(Alog, Dv);                       // 3 <- profiled
        }
        mma_gemm_a<<<dim3(64, 24), 256, MMASMEM>>>(
            winh + (size_t)lyr * NIN_W, winl + (size_t)lyr * NIN_W, hnh, hnl, xz, DM, BLTOK);
        conv_silu_kernel<<<(DI * BLTOK + 255) / 256, 256>>>(convw + lyr * DI * 4, convb + lyr * DI);
        sgemm_xproj<<<dim3(64, 3), 256>>>(
            xpW + (long)lyr * (DTR + 2 * DS) * DI, xconv, dt, DTR + 2 * DS, BLTOK, DI, BcT, CcT);
        sgemm_dtproj<<<dim3(64, 12), 256>>>(
            dtW + (long)lyr * DI * DTR, dt, delta, DI, BLTOK, DTR, dtb + lyr * DI);
        scanA_kernel<<<SCAN_WARPS / 4, 128>>>(Alog + (long)lyr * DI * DS);
        scanB_kernel<<<SCANB_WARPS / 4, 128>>>();
        scanC_kernel<<<SCAN_WARPS / 4, 128>>>(Alog + (long)lyr * DI * DS, Dv + lyr * DI);
        tcvt_kernel<<<dim3(BLTOK / 32, DI / 32), 256>>>(y, yh, yl);
        mma_gemm_b<<<dim3(64, 6), 256, MMASMEM>>>(
            wouth + (size_t)lyr * NOUT_W, woutl + (size_t)lyr * NOUT_W, yh, yl, h, DI, DM);
    }

    resln_kernel<<<BLTOK, 256>>>(h, res, out, nullptr, nullptr, nfw, nfb, 1);
}

// round 15
// speedup vs baseline: 1.1839x; 1.0795x over previous
#include <cuda_runtime.h>
#include <cuda_bf16.h>
#include <math.h>
#include <stdint.h>

#define L_SEQ  4096
#define NB     2
#define BLTOK  8192
#define DM     768
#define DI     1536
#define DS     16
#define DTR    48
#define NLAYER 4

#define NIN_W  (2 * DI * DM)
#define NOUT_W (DM * DI)

#define SCH 64
#define SCL 64

// ---------------- scratch ----------------
__device__ float g_h    [BLTOK * DM];
__device__ float g_res  [BLTOK * DM];
__device__ float g_xz   [2 * DI * BLTOK];   // (channel, token)
__device__ float g_xconv[DI * BLTOK];
__device__ float g_dt   [DTR * BLTOK];
__device__ float g_BcT  [BLTOK * DS];       // (token, n) — coalesced half-warp reads
__device__ float g_CcT  [BLTOK * DS];
__device__ float g_delta[DI * BLTOK];
__device__ float g_y    [DI * BLTOK];       // (channel, token)

__device__ float g_P [NB * SCH * DI * DS];
__device__ float g_Q [NB * SCH * DI * DS];
__device__ float g_S0[NB * SCH * DI * DS];

__device__ __nv_bfloat16 g_WinHi[NLAYER * NIN_W],  g_WinLo[NLAYER * NIN_W];
__device__ __nv_bfloat16 g_WoutHi[NLAYER * NOUT_W], g_WoutLo[NLAYER * NOUT_W];
__device__ __nv_bfloat16 g_hnHi[BLTOK * DM],  g_hnLo[BLTOK * DM];
__device__ __nv_bfloat16 g_yHi[BLTOK * DI],   g_yLo[BLTOK * DI];

// ---------------- helpers ----------------
__device__ __forceinline__ uint32_t smem_u32(const void* p) {
    uint32_t a;
    asm("{ .reg .u64 t; cvta.to.shared.u64 t, %1; cvt.u32.u64 %0, t; }" : "=r"(a) : "l"(p));
    return a;
}
#define LDSM_X4(r0, r1, r2, r3, a) \
    asm volatile("ldmatrix.sync.aligned.m8n8.x4.shared.b16 {%0,%1,%2,%3}, [%4];" \
                 : "=r"(r0), "=r"(r1), "=r"(r2), "=r"(r3) : "r"(a))
#define MMA_BF16(c, a0, a1, a2, a3, b0, b1) \
    asm volatile("mma.sync.aligned.m16n8k16.row.col.f32.bf16.bf16.f32 " \
                 "{%0,%1,%2,%3}, {%4,%5,%6,%7}, {%8,%9}, {%0,%1,%2,%3};" \
                 : "+f"((c)[0]), "+f"((c)[1]), "+f"((c)[2]), "+f"((c)[3]) \
                 : "r"(a0), "r"(a1), "r"(a2), "r"(a3), "r"(b0), "r"(b1))
#define CP_A16(dst, src) \
    asm volatile("cp.async.cg.shared.global [%0], [%1], 16;" :: "r"(dst), "l"(src))
#define CP_COMMIT()  asm volatile("cp.async.commit_group;")
#define CP_WAIT(n)   asm volatile("cp.async.wait_group %0;" :: "n"(n))

// ---------------- mma.sync 3xBF16 GEMM ----------------
#define TILE_B  10240
#define STAGE_B 40960
#define EPI_STRIDE 130
#define MMASMEM 81920

template <int LAYOUT>
__device__ __forceinline__ void mma_gemm_body(
    char* dsm,
    const __nv_bfloat16* __restrict__ Ahi, const __nv_bfloat16* __restrict__ Alo,
    const __nv_bfloat16* __restrict__ Bhi, const __nv_bfloat16* __restrict__ Blo,
    float* __restrict__ C, int K, int ldc) {
    const int tid = threadIdx.x;
    const int wid = tid >> 5;
    const int lane = tid & 31;
    const int bm = blockIdx.y * 128;
    const int bn = blockIdx.x * 128;
    const int wm = (wid >> 2) * 64;
    const int wn = (wid & 3) * 32;

    const uint32_t sb = smem_u32(dsm);

    uint32_t so[2];
    size_t offA[2], offB[2];
#pragma unroll
    for (int j = 0; j < 2; j++) {
        int v = tid + j * 256;
        int row = v >> 2, c = v & 3;
        so[j] = row * 80 + c * 16;
        offA[j] = (size_t)(bm + row) * K + c * 8;
        offB[j] = (size_t)(bn + row) * K + c * 8;
    }

    uint32_t aoff[4], boff[2];
    {
        int g = lane >> 3, r = lane & 7;
#pragma unroll
        for (int mt = 0; mt < 4; mt++) {
            int row = wm + mt * 16 + (g & 1) * 8 + r;
            aoff[mt] = row * 80 + (g >> 1) * 16;
        }
#pragma unroll
        for (int p = 0; p < 2; p++) {
            int row = wn + p * 16 + (g >> 1) * 8 + r;
            boff[p] = row * 80 + (g & 1) * 16;
        }
    }

    const int KT = K >> 5;

    auto issue = [&](int kc, int stg) {
        int k0 = kc << 5;
        uint32_t base = sb + stg * STAGE_B;
#pragma unroll
        for (int j = 0; j < 2; j++) {
            uint32_t d = base + so[j];
            CP_A16(d,              Ahi + offA[j] + k0);
            CP_A16(d + TILE_B,     Alo + offA[j] + k0);
            CP_A16(d + 2 * TILE_B, Bhi + offB[j] + k0);
            CP_A16(d + 3 * TILE_B, Blo + offB[j] + k0);
        }
        CP_COMMIT();
    };

    float acc[4][4][4];
#pragma unroll
    for (int mt = 0; mt < 4; mt++)
#pragma unroll
        for (int nt = 0; nt < 4; nt++)
#pragma unroll
            for (int e = 0; e < 4; e++) acc[mt][nt][e] = 0.f;

    issue(0, 0);
    if (KT > 1) issue(1, 1);

    for (int kc = 0; kc < KT; kc++) {
        if (kc + 1 < KT) CP_WAIT(1); else CP_WAIT(0);
        __syncthreads();
        uint32_t base = sb + (kc & 1) * STAGE_B;
        uint32_t sAh = base, sAl = base + TILE_B, sBh = base + 2 * TILE_B, sBl = base + 3 * TILE_B;
#pragma unroll
        for (int ks = 0; ks < 2; ks++) {
            uint32_t kb = ks * 32;
            uint32_t bh[2][4], bl[2][4];
#pragma unroll
            for (int p = 0; p < 2; p++) {
                LDSM_X4(bh[p][0], bh[p][1], bh[p][2], bh[p][3], sBh + boff[p] + kb);
                LDSM_X4(bl[p][0], bl[p][1], bl[p][2], bl[p][3], sBl + boff[p] + kb);
            }
#pragma unroll
            for (int mt = 0; mt < 4; mt++) {
                uint32_t ah[4], al[4];
                LDSM_X4(ah[0], ah[1], ah[2], ah[3], sAh + aoff[mt] + kb);
                LDSM_X4(al[0], al[1], al[2], al[3], sAl + aoff[mt] + kb);
#pragma unroll
                for (int nt = 0; nt < 4; nt++) {
                    int p = nt >> 1, h = (nt & 1) * 2;
                    MMA_BF16(acc[mt][nt], ah[0], ah[1], ah[2], ah[3], bh[p][h], bh[p][h + 1]);
                    MMA_BF16(acc[mt][nt], ah[0], ah[1], ah[2], ah[3], bl[p][h], bl[p][h + 1]);
                    MMA_BF16(acc[mt][nt], al[0], al[1], al[2], al[3], bh[p][h], bh[p][h + 1]);
                }
            }
        }
        __syncthreads();
        if (kc + 2 < KT) issue(kc + 2, kc & 1);
    }

    float* st = (float*)dsm;
    {
        int mr = lane >> 2;
        int nc = (lane & 3) * 2;
#pragma unroll
        for (int mt = 0; mt < 4; mt++) {
#pragma unroll
            for (int nt = 0; nt < 4; nt++) {
                int m0 = wm + mt * 16 + mr;
                int n0 = wn + nt * 8 + nc;
                *(float2*)(st + m0 * EPI_STRIDE + n0) = make_float2(acc[mt][nt][0], acc[mt][nt][1]);
                *(float2*)(st + (m0 + 8) * EPI_STRIDE + n0) = make_float2(acc[mt][nt][2], acc[mt][nt][3]);
            }
        }
    }
    __syncthreads();
    if (LAYOUT == 0) {
        for (int idx = tid; idx < 16384; idx += 256) {
            int r = idx >> 7, c = idx & 127;
            C[(size_t)(bm + r) * ldc + bn + c] = st[r * EPI_STRIDE + c];
        }
    } else {
        for (int idx = tid; idx < 16384; idx += 256) {
            int n = idx >> 7, m = idx & 127;
            C[(size_t)(bn + n) * ldc + bm + m] = st[m * EPI_STRIDE + n];
        }
    }
}

__global__ void __launch_bounds__(256, 2) mma_gemm_a(
    const __nv_bfloat16* __restrict__ Ahi, const __nv_bfloat16* __restrict__ Alo,
    const __nv_bfloat16* __restrict__ Bhi, const __nv_bfloat16* __restrict__ Blo,
    float* __restrict__ C, int K, int ldc) {
    extern __shared__ char dsm[];
    mma_gemm_body<0>(dsm, Ahi, Alo, Bhi, Blo, C, K, ldc);
}
__global__ void __launch_bounds__(256, 2) mma_gemm_b(
    const __nv_bfloat16* __restrict__ Ahi, const __nv_bfloat16* __restrict__ Alo,
    const __nv_bfloat16* __restrict__ Bhi, const __nv_bfloat16* __restrict__ Blo,
    float* __restrict__ C, int K, int ldc) {
    extern __shared__ char dsm[];
    mma_gemm_body<1>(dsm, Ahi, Alo, Bhi, Blo, C, K, ldc);
}

// ---------------- all-layer weight fp32 -> bf16 hi/lo ----------------
#define CVT_TOTAL (NLAYER * (NIN_W + NOUT_W))
__global__ void cvt_all_kernel(const float* __restrict__ inW, const float* __restrict__ outW) {
    int i = blockIdx.x * 256 + threadIdx.x;
    if (i >= CVT_TOTAL) return;
    float v;
    __nv_bfloat16 *hi, *lo;
    if (i < NLAYER * NIN_W) {
        v = inW[i];
        hi = g_WinHi + i; lo = g_WinLo + i;
    } else {
        int j = i - NLAYER * NIN_W;
        v = outW[j];
        hi = g_WoutHi + j; lo = g_WoutLo + j;
    }
    __nv_bfloat16 h = __float2bfloat16(v);
    *hi = h;
    *lo = __float2bfloat16(v - __bfloat162float(h));
}

// ---------------- transpose (d,tok)->(tok,d) + bf16 hi/lo ----------------
__global__ void tcvt_kernel(const float* __restrict__ src, __nv_bfloat16* __restrict__ hi,
                            __nv_bfloat16* __restrict__ lo) {
    __shared__ float t[32][33];
    int tx = threadIdx.x & 31, ty = threadIdx.x >> 5;
    int tok0 = blockIdx.x * 32, d0 = blockIdx.y * 32;
#pragma unroll
    for (int i = 0; i < 4; i++) {
        int d = d0 + ty + i * 8;
        t[ty + i * 8][tx] = src[(size_t)d * BLTOK + tok0 + tx];
    }
    __syncthreads();
#pragma unroll
    for (int i = 0; i < 4; i++) {
        int tok = tok0 + ty + i * 8;
        float v = t[tx][ty + i * 8];
        __nv_bfloat16 h = __float2bfloat16(v);
        size_t o = (size_t)tok * DI + d0 + tx;
        hi[o] = h;
        lo[o] = __float2bfloat16(v - __bfloat162float(h));
    }
}

// ---------------- embed ----------------
__global__ void embed_kernel(const float* __restrict__ x, const float* __restrict__ W,
                             const float* __restrict__ bias) {
    __shared__ float xs[64];
    int tok = blockIdx.x;
    int b = tok >> 12, l = tok & 4095;
    int tid = threadIdx.x;
    if (tid < 64) xs[tid] = x[(b * 64 + tid) * L_SEQ + l];
    __syncthreads();
    for (int e = tid; e < DM; e += 256) {
        const float* w = W + e * 64;
        float acc = bias[e];
#pragma unroll 16
        for (int i = 0; i < 64; i++) acc = fmaf(w[i], xs[i], acc);
        g_h[tok * DM + e] = acc;
    }
}

// ---------------- fused residual + layernorm ----------------
__global__ void resln_kernel(const float* __restrict__ src, float* __restrict__ res,
                             float* __restrict__ outf, __nv_bfloat16* __restrict__ ohi,
                             __nv_bfloat16* __restrict__ olo,
                             const float* __restrict__ w, const float* __restrict__ b, int add) {
    __shared__ float red1[8], red2[8];
    int base = blockIdx.x * DM;
    int tid = threadIdx.x;
    float v0 = src[base + tid];
    float v1 = src[base + tid + 256];
    float v2 = src[base + tid + 512];
    if (add) {
        v0 += res[base + tid];
        v1 += res[base + tid + 256];
        v2 += res[base + tid + 512];
    }
    res[base + tid]       = v0;
    res[base + tid + 256] = v1;
    res[base + tid + 512] = v2;

    float s = v0 + v1 + v2;
#pragma unroll
    for (int o = 16; o; o >>= 1) s += __shfl_xor_sync(0xffffffffu, s, o);
    if ((tid & 31) == 0) red1[tid >> 5] = s;
    __syncthreads();
    float tot = 0.f;
#pragma unroll
    for (int i = 0; i < 8; i++) tot += red1[i];
    float mean = tot * (1.f / DM);

    float d0 = v0 - mean, d1 = v1 - mean, d2 = v2 - mean;
    float sq = d0 * d0 + d1 * d1 + d2 * d2;
#pragma unroll
    for (int o = 16; o; o >>= 1) sq += __shfl_xor_sync(0xffffffffu, sq, o);
    if ((tid & 31) == 0) red2[tid >> 5] = sq;
    __syncthreads();
    float vt = 0.f;
#pragma unroll
    for (int i = 0; i < 8; i++) vt += red2[i];
    float inv = rsqrtf(vt * (1.f / DM) + 1e-5f);

    float o0 = d0 * inv * w[tid]       + b[tid];
    float o1 = d1 * inv * w[tid + 256] + b[tid + 256];
    float o2 = d2 * inv * w[tid + 512] + b[tid + 512];
    if (outf) {
        outf[base + tid]       = o0;
        outf[base + tid + 256] = o1;
        outf[base + tid + 512] = o2;
    } else {
        __nv_bfloat16 h0 = __float2bfloat16(o0), h1 = __float2bfloat16(o1), h2 = __float2bfloat16(o2);
        ohi[base + tid]       = h0;  olo[base + tid]       = __float2bfloat16(o0 - __bfloat162float(h0));
        ohi[base + tid + 256] = h1;  olo[base + tid + 256] = __float2bfloat16(o1 - __bfloat162float(h1));
        ohi[base + tid + 512] = h2;  olo[base + tid + 512] = __float2bfloat16(o2 - __bfloat162float(h2));
    }
}

// ---------------- SIMT SGEMM (x_proj / dt_proj) ----------------
#define BK 16
#define SPAD 4
enum { EPI_STORE = 0, EPI_SOFTPLUS = 1, EPI_TRANS = 2, EPI_XPROJ = 3 };

template <int BM, int BN, int TM, int TN, bool BNT, int EPI>
__device__ __forceinline__ void sgemm_body(
    const float* __restrict__ A, const float* __restrict__ B, float* __restrict__ C,
    int M, int N, int K, const float* __restrict__ bias,
    float* __restrict__ aux1, float* __restrict__ aux2) {
    constexpr int AE = BM * BK / 256;
    constexpr int BE = BN * BK / 256;
    __shared__ float As[BK][BM + SPAD];
    __shared__ float Bs[BK][BN + SPAD];

    int tid = threadIdx.x;
    int bm = blockIdx.y * BM;
    int bn = blockIdx.x * BN;
    int tx = tid % (BN / TN);
    int ty = tid / (BN / TN);

    float acc[TM][TN];
#pragma unroll
    for (int i = 0; i < TM; i++)
#pragma unroll
        for (int j = 0; j < TN; j++) acc[i][j] = 0.f;

    float pa[AE], pb[BE];
    auto loadA = [&](int k0) {
#pragma unroll
        for (int e = 0; e < AE; e++) {
            int i = tid + e * 256;
            int r = i / BK, kk = i % BK;
            int m = bm + r;
            pa[e] = (m < M) ? A[(long)m * K + k0 + kk] : 0.f;
        }
    };
    auto loadB = [&](int k0) {
#pragma unroll
        for (int e = 0; e < BE; e++) {
            int i = tid + e * 256;
            if (BNT) {
                int r = i / BK, kk = i % BK;
                pb[e] = B[(long)(bn + r) * K + k0 + kk];
            } else {
                int kk = i / BN, c = i % BN;
                pb[e] = B[(long)(k0 + kk) * N + bn + c];
            }
        }
    };
    auto storeAB = [&]() {
#pragma unroll
        for (int e = 0; e < AE; e++) {
            int i = tid + e * 256;
            As[i % BK][i / BK] = pa[e];
        }
#pragma unroll
        for (int e = 0; e < BE; e++) {
            int i = tid + e * 256;
            if (BNT) Bs[i % BK][i / BK] = pb[e];
            else     Bs[i / BN][i % BN] = pb[e];
        }
    };

    int KT = K / BK;
    loadA(0); loadB(0);
    storeAB();
    __syncthreads();

    for (int kt = 0; kt < KT; kt++) {
        if (kt + 1 < KT) { loadA((kt + 1) * BK); loadB((kt + 1) * BK); }
#pragma unroll
        for (int kk = 0; kk < BK; kk++) {
            float a[TM], bf[TN];
#pragma unroll
            for (int i = 0; i < TM; i++) a[i] = As[kk][ty * TM + i];
#pragma unroll
            for (int j = 0; j < TN; j++) bf[j] = Bs[kk][tx * TN + j];
#pragma unroll
            for (int i = 0; i < TM; i++)
#pragma unroll
                for (int j = 0; j < TN; j++) acc[i][j] = fmaf(a[i], bf[j], acc[i][j]);
        }
        __syncthreads();
        if (kt + 1 < KT) {
            storeAB();
            __syncthreads();
        }
    }

#pragma unroll
    for (int i = 0; i < TM; i++) {
        int m = bm + ty * TM + i;
        if (m >= M) continue;
#pragma unroll
        for (int j = 0; j < TN; j++) {
            int n = bn + tx * TN + j;
            float v = acc[i][j];
            if (EPI == EPI_STORE) {
                C[(long)m * N + n] = v;
            } else if (EPI == EPI_SOFTPLUS) {
                v += bias[m];
                C[(long)m * N + n] = (v > 20.f) ? v : __logf(1.f + __expf(v));
            } else if (EPI == EPI_TRANS) {
                C[(long)n * M + m] = v;
            } else { // EPI_XPROJ: Bc/Cc stored (token, n)
                if (m < DTR)            C[(long)m * N + n] = v;
                else if (m < DTR + DS)  aux1[(long)n * DS + (m - DTR)] = v;
                else                    aux2[(long)n * DS + (m - DTR - DS)] = v;
            }
        }
    }
}

__global__ void __launch_bounds__(256, 2) sgemm_xproj(
    const float* __restrict__ A, const float* __restrict__ B, float* __restrict__ C,
    int M, int N, int K, float* __restrict__ aux1, float* __restrict__ aux2) {
    sgemm_body<32, 128, 2, 8, false, EPI_XPROJ>(A, B, C, M, N, K, nullptr, aux1, aux2);
}
__global__ void __launch_bounds__(256, 2) sgemm_dtproj(
    const float* __restrict__ A, const float* __restrict__ B, float* __restrict__ C,
    int M, int N, int K, const float* __restrict__ bias) {
    sgemm_body<128, 128, 8, 8, false, EPI_SOFTPLUS>(A, B, C, M, N, K, bias, nullptr, nullptr);
}

// ---------------- depthwise causal conv1d + bias + SiLU ----------------
__global__ void conv_silu_kernel(const float* __restrict__ cw, const float* __restrict__ cb) {
    int idx = blockIdx.x * 256 + threadIdx.x;
    if (idx >= DI * BLTOK) return;
    int d = idx >> 13;
    int bl = idx & 8191;
    int l = bl & 4095;
    const float* xp = g_xz + (long)d * BLTOK + bl;
    float w0 = cw[d * 4], w1 = cw[d * 4 + 1], w2 = cw[d * 4 + 2], w3 = cw[d * 4 + 3];
    float acc = cb[d];
    if (l >= 3) acc = fmaf(w0, xp[-3], acc);
    if (l >= 2) acc = fmaf(w1, xp[-2], acc);
    if (l >= 1) acc = fmaf(w2, xp[-1], acc);
    acc = fmaf(w3, xp[0], acc);
    float sg = 1.f / (1.f + __expf(-acc));
    g_xconv[idx] = acc * sg;
}

// ---------------- chunked scan pass A: float4 broadcast de/u, scalar coalesced B ----------------
__global__ void scanA_kernel(const float* __restrict__ A_log) {
    int g = blockIdx.x * (blockDim.x >> 5) + (threadIdx.x >> 5);
    int lane = threadIdx.x & 31;
    int c  = g % SCH;
    int dp = (g / SCH) % (DI / 2);
    int b  = g / (SCH * (DI / 2));
    int half = lane >> 4;
    int n = lane & 15;
    int d = dp * 2 + half;

    float Acoef = -expf(A_log[d * DS + n]);

    size_t tbase = (size_t)b * L_SEQ + c * SCL;
    const float4* dp4 = (const float4*)(g_delta + (size_t)d * BLTOK + tbase);
    const float4* up4 = (const float4*)(g_xconv + (size_t)d * BLTOK + tbase);
    const float* bptr = g_BcT + tbase * DS + n;

    float P = 1.f, s = 0.f;
#pragma unroll 4
    for (int tg = 0; tg < SCL / 4; tg++) {
        float4 de4 = dp4[tg], u4 = up4[tg];
#define ASTEP(cmp, t) { float Bn = bptr[(size_t)(tg * 4 + t) * DS]; \
                        float dA = __expf(de4.cmp * Acoef); P *= dA; \
                        s = fmaf(dA, s, de4.cmp * u4.cmp * Bn); }
        ASTEP(x, 0) ASTEP(y, 1) ASTEP(z, 2) ASTEP(w, 3)
#undef ASTEP
    }
    size_t o = (((size_t)b * SCH + c) * DI + d) * DS + n;
    g_P[o] = P;
    g_Q[o] = s;
}

// ---------------- pass B ----------------
__global__ void scanB_kernel() {
    int g = blockIdx.x * (blockDim.x >> 5) + (threadIdx.x >> 5);
    int lane = threadIdx.x & 31;
    int dp = g % (DI / 2);
    int b  = g / (DI / 2);
    int half = lane >> 4;
    int n = lane & 15;
    int d = dp * 2 + half;

    float s = 0.f;
    size_t stride = (size_t)DI * DS;
    size_t o = (((size_t)b * SCH) * DI + d) * DS + n;
#pragma unroll 4
    for (int c = 0; c < SCH; c++) {
        g_S0[o] = s;
        s = fmaf(g_P[o], s, g_Q[o]);
        o += stride;
    }
}

// ---------------- pass C: float4 broadcast de/u/z, scalar coalesced B/C ----------------
__global__ void scanC_kernel(const float* __restrict__ A_log, const float* __restrict__ Dvec) {
    int g = blockIdx.x * (blockDim.x >> 5) + (threadIdx.x >> 5);
    int lane = threadIdx.x & 31;
    int c  = g % SCH;
    int dp = (g / SCH) % (DI / 2);
    int b  = g / (SCH * (DI / 2));
    int half = lane >> 4;
    int n = lane & 15;
    int d = dp * 2 + half;

    float Acoef = -expf(A_log[d * DS + n]);
    float Dv = Dvec[d];

    size_t tbase = (size_t)b * L_SEQ + c * SCL;
    const float4* dp4 = (const float4*)(g_delta + (size_t)d * BLTOK + tbase);
    const float4* up4 = (const float4*)(g_xconv + (size_t)d * BLTOK + tbase);
    const float4* zp4 = (const float4*)(g_xz + (size_t)(DI + d) * BLTOK + tbase);
    const float* bptr = g_BcT + tbase * DS + n;
    const float* cptr = g_CcT + tbase * DS + n;
    float* yptr = g_y + (size_t)d * BLTOK + tbase;

    float s = g_S0[(((size_t)b * SCH + c) * DI + d) * DS + n];
#pragma unroll 2
    for (int tg = 0; tg < SCL / 4; tg++) {
        float4 de4 = dp4[tg], u4 = up4[tg], z4 = zp4[tg];
#define CSTEP(cmp, t) { int tt = tg * 4 + t; \
                        float Bn = bptr[(size_t)tt * DS]; \
                        float Cn = cptr[(size_t)tt * DS]; \
                        float dA = __expf(de4.cmp * Acoef); \
                        s = fmaf(dA, s, de4.cmp * u4.cmp * Bn); \
                        float p = s * Cn; \
                        p += __shfl_xor_sync(0xffffffffu, p, 8, 16); \
                        p += __shfl_xor_sync(0xffffffffu, p, 4, 16); \
                        p += __shfl_xor_sync(0xffffffffu, p, 2, 16); \
                        p += __shfl_xor_sync(0xffffffffu, p, 1, 16); \
                        float yv = fmaf(Dv, u4.cmp, p); \
                        float sg = 1.f / (1.f + __expf(-z4.cmp)); \
                        yv *= z4.cmp * sg; \
                        if (n == 0) yptr[tt] = yv; }
        CSTEP(x, 0) CSTEP(y, 1) CSTEP(z, 2) CSTEP(w, 3)
#undef CSTEP
    }
}

// ---------------- host launcher ----------------
extern "C" void kernel_launch(void* const* d_in, const int* in_sizes, int n_in,
                              void* d_out, int out_size) {
    const float* x     = (const float*)d_in[0];
    const float* embW  = (const float*)d_in[1];
    const float* embB  = (const float*)d_in[2];
    const float* normw = (const float*)d_in[3];
    const float* normb = (const float*)d_in[4];
    const float* inW   = (const float*)d_in[5];
    const float* convw = (const float*)d_in[6];
    const float* convb = (const float*)d_in[7];
    const float* xpW   = (const float*)d_in[8];
    const float* dtW   = (const float*)d_in[9];
    const float* dtb   = (const float*)d_in[10];
    const float* Alog  = (const float*)d_in[11];
    const float* Dv    = (const float*)d_in[12];
    const float* outW  = (const float*)d_in[13];
    const float* nfw   = (const float*)d_in[14];
    const float* nfb   = (const float*)d_in[15];
    float* out = (float*)d_out;

    float *h, *res, *xz, *xconv, *dt, *BcT, *CcT, *delta, *y;
    __nv_bfloat16 *winh, *winl, *wouth, *woutl, *hnh, *hnl, *yh, *yl;
    cudaGetSymbolAddress((void**)&h,     g_h);
    cudaGetSymbolAddress((void**)&res,   g_res);
    cudaGetSymbolAddress((void**)&xz,    g_xz);
    cudaGetSymbolAddress((void**)&xconv, g_xconv);
    cudaGetSymbolAddress((void**)&dt,    g_dt);
    cudaGetSymbolAddress((void**)&BcT,   g_BcT);
    cudaGetSymbolAddress((void**)&CcT,   g_CcT);
    cudaGetSymbolAddress((void**)&delta, g_delta);
    cudaGetSymbolAddress((void**)&y,     g_y);
    cudaGetSymbolAddress((void**)&winh,  g_WinHi);
    cudaGetSymbolAddress((void**)&winl,  g_WinLo);
    cudaGetSymbolAddress((void**)&wouth, g_WoutHi);
    cudaGetSymbolAddress((void**)&woutl, g_WoutLo);
    cudaGetSymbolAddress((void**)&hnh,   g_hnHi);
    cudaGetSymbolAddress((void**)&hnl,   g_hnLo);
    cudaGetSymbolAddress((void**)&yh,    g_yHi);
    cudaGetSymbolAddress((void**)&yl,    g_yLo);

    cudaFuncSetAttribute(mma_gemm_a, cudaFuncAttributeMaxDynamicSharedMemorySize, MMASMEM);
    cudaFuncSetAttribute(mma_gemm_b, cudaFuncAttributeMaxDynamicSharedMemorySize, MMASMEM);

    const int SCAN_WARPS = NB * (DI / 2) * SCH;
    const int SCANB_WARPS = NB * (DI / 2);

    embed_kernel<<<BLTOK, 256>>>(x, embW, embB);
    cvt_all_kernel<<<(CVT_TOTAL + 255) / 256, 256>>>(inW, outW);

    for (int lyr = 0; lyr < NLAYER; lyr++) {
        resln_kernel<<<BLTOK, 256>>>(h, res, nullptr, hnh, hnl,
                                     normw + lyr * DM, normb + lyr * DM, lyr > 0 ? 1 : 0);
        mma_gemm_a<<<dim3(64, 24), 256, MMASMEM>>>(
            winh + (size_t)lyr * NIN_W, winl + (size_t)lyr * NIN_W, hnh, hnl, xz, DM, BLTOK);
        conv_silu_kernel<<<(DI * BLTOK + 255) / 256, 256>>>(convw + lyr * DI * 4, convb + lyr * DI);
        sgemm_xproj<<<dim3(64, 3), 256>>>(
            xpW + (long)lyr * (DTR + 2 * DS) * DI, xconv, dt, DTR + 2 * DS, BLTOK, DI, BcT, CcT);
        sgemm_dtproj<<<dim3(64, 12), 256>>>(
            dtW + (long)lyr * DI * DTR, dt, delta, DI, BLTOK, DTR, dtb + lyr * DI);
        scanA_kernel<<<SCAN_WARPS / 4, 128>>>(Alog + (long)lyr * DI * DS);
        scanB_kernel<<<SCANB_WARPS / 4, 128>>>();
        scanC_kernel<<<SCAN_WARPS / 4, 128>>>(Alog + (long)lyr * DI * DS, Dv + lyr * DI);
        tcvt_kernel<<<dim3(BLTOK / 32, DI / 32), 256>>>(y, yh, yl);
        mma_gemm_b<<<dim3(64, 6), 256, MMASMEM>>>(
            wouth + (size_t)lyr * NOUT_W, woutl + (size_t)lyr * NOUT_W, yh, yl, h, DI, DM);
    }

    resln_kernel<<<BLTOK, 256>>>(h, res, out, nullptr, nullptr, nfw, nfb, 1);
}

// round 16
// speedup vs baseline: 1.2348x; 1.0430x over previous
#include <cuda_runtime.h>
#include <cuda_bf16.h>
#include <math.h>
#include <stdint.h>

#define L_SEQ  4096
#define NB     2
#define BLTOK  8192
#define DM     768
#define DI     1536
#define DS     16
#define DTR    48
#define NLAYER 4

#define NIN_W  (2 * DI * DM)
#define NOUT_W (DM * DI)

#define SCH 64
#define SCL 64

#define XP_M     80
#define XP_KSPL  4
#define XP_KCH   (DI / XP_KSPL)      // 384
#define XP_PART  (XP_M * BLTOK)

// ---------------- scratch ----------------
__device__ float g_h    [BLTOK * DM];
__device__ float g_res  [BLTOK * DM];
__device__ float g_xz   [2 * DI * BLTOK];   // (channel, token)
__device__ float g_xconv[DI * BLTOK];
__device__ float g_dt   [DTR * BLTOK];
__device__ float g_BcT  [BLTOK * DS];       // (token, n)
__device__ float g_CcT  [BLTOK * DS];
__device__ float g_delta[DI * BLTOK];
__device__ float g_y    [DI * BLTOK];       // (channel, token)
__device__ float g_xpPart[XP_KSPL * XP_PART];

__device__ float g_P [NB * SCH * DI * DS];
__device__ float g_Q [NB * SCH * DI * DS];
__device__ float g_S0[NB * SCH * DI * DS];

__device__ __nv_bfloat16 g_WinHi[NLAYER * NIN_W],  g_WinLo[NLAYER * NIN_W];
__device__ __nv_bfloat16 g_WoutHi[NLAYER * NOUT_W], g_WoutLo[NLAYER * NOUT_W];
__device__ __nv_bfloat16 g_hnHi[BLTOK * DM],  g_hnLo[BLTOK * DM];
__device__ __nv_bfloat16 g_yHi[BLTOK * DI],   g_yLo[BLTOK * DI];

// ---------------- helpers ----------------
__device__ __forceinline__ uint32_t smem_u32(const void* p) {
    uint32_t a;
    asm("{ .reg .u64 t; cvta.to.shared.u64 t, %1; cvt.u32.u64 %0, t; }" : "=r"(a) : "l"(p));
    return a;
}
#define LDSM_X4(r0, r1, r2, r3, a) \
    asm volatile("ldmatrix.sync.aligned.m8n8.x4.shared.b16 {%0,%1,%2,%3}, [%4];" \
                 : "=r"(r0), "=r"(r1), "=r"(r2), "=r"(r3) : "r"(a))
#define MMA_BF16(c, a0, a1, a2, a3, b0, b1) \
    asm volatile("mma.sync.aligned.m16n8k16.row.col.f32.bf16.bf16.f32 " \
                 "{%0,%1,%2,%3}, {%4,%5,%6,%7}, {%8,%9}, {%0,%1,%2,%3};" \
                 : "+f"((c)[0]), "+f"((c)[1]), "+f"((c)[2]), "+f"((c)[3]) \
                 : "r"(a0), "r"(a1), "r"(a2), "r"(a3), "r"(b0), "r"(b1))
#define CP_A16(dst, src) \
    asm volatile("cp.async.cg.shared.global [%0], [%1], 16;" :: "r"(dst), "l"(src))
#define CP_COMMIT()  asm volatile("cp.async.commit_group;")
#define CP_WAIT(n)   asm volatile("cp.async.wait_group %0;" :: "n"(n))

// ---------------- mma.sync 3xBF16 GEMM ----------------
#define TILE_B  10240
#define STAGE_B 40960
#define EPI_STRIDE 130
#define MMASMEM 81920

template <int LAYOUT>
__device__ __forceinline__ void mma_gemm_body(
    char* dsm,
    const __nv_bfloat16* __restrict__ Ahi, const __nv_bfloat16* __restrict__ Alo,
    const __nv_bfloat16* __restrict__ Bhi, const __nv_bfloat16* __restrict__ Blo,
    float* __restrict__ C, int K, int ldc) {
    const int tid = threadIdx.x;
    const int wid = tid >> 5;
    const int lane = tid & 31;
    const int bm = blockIdx.y * 128;
    const int bn = blockIdx.x * 128;
    const int wm = (wid >> 2) * 64;
    const int wn = (wid & 3) * 32;

    const uint32_t sb = smem_u32(dsm);

    uint32_t so[2];
    size_t offA[2], offB[2];
#pragma unroll
    for (int j = 0; j < 2; j++) {
        int v = tid + j * 256;
        int row = v >> 2, c = v & 3;
        so[j] = row * 80 + c * 16;
        offA[j] = (size_t)(bm + row) * K + c * 8;
        offB[j] = (size_t)(bn + row) * K + c * 8;
    }

    uint32_t aoff[4], boff[2];
    {
        int g = lane >> 3, r = lane & 7;
#pragma unroll
        for (int mt = 0; mt < 4; mt++) {
            int row = wm + mt * 16 + (g & 1) * 8 + r;
            aoff[mt] = row * 80 + (g >> 1) * 16;
        }
#pragma unroll
        for (int p = 0; p < 2; p++) {
            int row = wn + p * 16 + (g >> 1) * 8 + r;
            boff[p] = row * 80 + (g & 1) * 16;
        }
    }

    const int KT = K >> 5;

    auto issue = [&](int kc, int stg) {
        int k0 = kc << 5;
        uint32_t base = sb + stg * STAGE_B;
#pragma unroll
        for (int j = 0; j < 2; j++) {
            uint32_t d = base + so[j];
            CP_A16(d,              Ahi + offA[j] + k0);
            CP_A16(d + TILE_B,     Alo + offA[j] + k0);
            CP_A16(d + 2 * TILE_B, Bhi + offB[j] + k0);
            CP_A16(d + 3 * TILE_B, Blo + offB[j] + k0);
        }
        CP_COMMIT();
    };

    float acc[4][4][4];
#pragma unroll
    for (int mt = 0; mt < 4; mt++)
#pragma unroll
        for (int nt = 0; nt < 4; nt++)
#pragma unroll
            for (int e = 0; e < 4; e++) acc[mt][nt][e] = 0.f;

    issue(0, 0);
    if (KT > 1) issue(1, 1);

    for (int kc = 0; kc < KT; kc++) {
        if (kc + 1 < KT) CP_WAIT(1); else CP_WAIT(0);
        __syncthreads();
        uint32_t base = sb + (kc & 1) * STAGE_B;
        uint32_t sAh = base, sAl = base + TILE_B, sBh = base + 2 * TILE_B, sBl = base + 3 * TILE_B;
#pragma unroll
        for (int ks = 0; ks < 2; ks++) {
            uint32_t kb = ks * 32;
            uint32_t bh[2][4], bl[2][4];
#pragma unroll
            for (int p = 0; p < 2; p++) {
                LDSM_X4(bh[p][0], bh[p][1], bh[p][2], bh[p][3], sBh + boff[p] + kb);
                LDSM_X4(bl[p][0], bl[p][1], bl[p][2], bl[p][3], sBl + boff[p] + kb);
            }
#pragma unroll
            for (int mt = 0; mt < 4; mt++) {
                uint32_t ah[4], al[4];
                LDSM_X4(ah[0], ah[1], ah[2], ah[3], sAh + aoff[mt] + kb);
                LDSM_X4(al[0], al[1], al[2], al[3], sAl + aoff[mt] + kb);
#pragma unroll
                for (int nt = 0; nt < 4; nt++) {
                    int p = nt >> 1, h = (nt & 1) * 2;
                    MMA_BF16(acc[mt][nt], ah[0], ah[1], ah[2], ah[3], bh[p][h], bh[p][h + 1]);
                    MMA_BF16(acc[mt][nt], ah[0], ah[1], ah[2], ah[3], bl[p][h], bl[p][h + 1]);
                    MMA_BF16(acc[mt][nt], al[0], al[1], al[2], al[3], bh[p][h], bh[p][h + 1]);
                }
            }
        }
        __syncthreads();
        if (kc + 2 < KT) issue(kc + 2, kc & 1);
    }

    float* st = (float*)dsm;
    {
        int mr = lane >> 2;
        int nc = (lane & 3) * 2;
#pragma unroll
        for (int mt = 0; mt < 4; mt++) {
#pragma unroll
            for (int nt = 0; nt < 4; nt++) {
                int m0 = wm + mt * 16 + mr;
                int n0 = wn + nt * 8 + nc;
                *(float2*)(st + m0 * EPI_STRIDE + n0) = make_float2(acc[mt][nt][0], acc[mt][nt][1]);
                *(float2*)(st + (m0 + 8) * EPI_STRIDE + n0) = make_float2(acc[mt][nt][2], acc[mt][nt][3]);
            }
        }
    }
    __syncthreads();
    if (LAYOUT == 0) {
        for (int idx = tid; idx < 16384; idx += 256) {
            int r = idx >> 7, c = idx & 127;
            C[(size_t)(bm + r) * ldc + bn + c] = st[r * EPI_STRIDE + c];
        }
    } else {
        for (int idx = tid; idx < 16384; idx += 256) {
            int n = idx >> 7, m = idx & 127;
            C[(size_t)(bn + n) * ldc + bm + m] = st[m * EPI_STRIDE + n];
        }
    }
}

__global__ void __launch_bounds__(256, 2) mma_gemm_a(
    const __nv_bfloat16* __restrict__ Ahi, const __nv_bfloat16* __restrict__ Alo,
    const __nv_bfloat16* __restrict__ Bhi, const __nv_bfloat16* __restrict__ Blo,
    float* __restrict__ C, int K, int ldc) {
    extern __shared__ char dsm[];
    mma_gemm_body<0>(dsm, Ahi, Alo, Bhi, Blo, C, K, ldc);
}
__global__ void __launch_bounds__(256, 2) mma_gemm_b(
    const __nv_bfloat16* __restrict__ Ahi, const __nv_bfloat16* __restrict__ Alo,
    const __nv_bfloat16* __restrict__ Bhi, const __nv_bfloat16* __restrict__ Blo,
    float* __restrict__ C, int K, int ldc) {
    extern __shared__ char dsm[];
    mma_gemm_body<1>(dsm, Ahi, Alo, Bhi, Blo, C, K, ldc);
}

// ---------------- all-layer weight fp32 -> bf16 hi/lo ----------------
#define CVT_TOTAL (NLAYER * (NIN_W + NOUT_W))
__global__ void cvt_all_kernel(const float* __restrict__ inW, const float* __restrict__ outW) {
    int i = blockIdx.x * 256 + threadIdx.x;
    if (i >= CVT_TOTAL) return;
    float v;
    __nv_bfloat16 *hi, *lo;
    if (i < NLAYER * NIN_W) {
        v = inW[i];
        hi = g_WinHi + i; lo = g_WinLo + i;
    } else {
        int j = i - NLAYER * NIN_W;
        v = outW[j];
        hi = g_WoutHi + j; lo = g_WoutLo + j;
    }
    __nv_bfloat16 h = __float2bfloat16(v);
    *hi = h;
    *lo = __float2bfloat16(v - __bfloat162float(h));
}

// ---------------- transpose (d,tok)->(tok,d) + bf16 hi/lo ----------------
__global__ void tcvt_kernel(const float* __restrict__ src, __nv_bfloat16* __restrict__ hi,
                            __nv_bfloat16* __restrict__ lo) {
    __shared__ float t[32][33];
    int tx = threadIdx.x & 31, ty = threadIdx.x >> 5;
    int tok0 = blockIdx.x * 32, d0 = blockIdx.y * 32;
#pragma unroll
    for (int i = 0; i < 4; i++) {
        int d = d0 + ty + i * 8;
        t[ty + i * 8][tx] = src[(size_t)d * BLTOK + tok0 + tx];
    }
    __syncthreads();
#pragma unroll
    for (int i = 0; i < 4; i++) {
        int tok = tok0 + ty + i * 8;
        float v = t[tx][ty + i * 8];
        __nv_bfloat16 h = __float2bfloat16(v);
        size_t o = (size_t)tok * DI + d0 + tx;
        hi[o] = h;
        lo[o] = __float2bfloat16(v - __bfloat162float(h));
    }
}

// ---------------- embed ----------------
__global__ void embed_kernel(const float* __restrict__ x, const float* __restrict__ W,
                             const float* __restrict__ bias) {
    __shared__ float xs[64];
    int tok = blockIdx.x;
    int b = tok >> 12, l = tok & 4095;
    int tid = threadIdx.x;
    if (tid < 64) xs[tid] = x[(b * 64 + tid) * L_SEQ + l];
    __syncthreads();
    for (int e = tid; e < DM; e += 256) {
        const float* w = W + e * 64;
        float acc = bias[e];
#pragma unroll 16
        for (int i = 0; i < 64; i++) acc = fmaf(w[i], xs[i], acc);
        g_h[tok * DM + e] = acc;
    }
}

// ---------------- fused residual + layernorm ----------------
__global__ void resln_kernel(const float* __restrict__ src, float* __restrict__ res,
                             float* __restrict__ outf, __nv_bfloat16* __restrict__ ohi,
                             __nv_bfloat16* __restrict__ olo,
                             const float* __restrict__ w, const float* __restrict__ b, int add) {
    __shared__ float red1[8], red2[8];
    int base = blockIdx.x * DM;
    int tid = threadIdx.x;
    float v0 = src[base + tid];
    float v1 = src[base + tid + 256];
    float v2 = src[base + tid + 512];
    if (add) {
        v0 += res[base + tid];
        v1 += res[base + tid + 256];
        v2 += res[base + tid + 512];
    }
    res[base + tid]       = v0;
    res[base + tid + 256] = v1;
    res[base + tid + 512] = v2;

    float s = v0 + v1 + v2;
#pragma unroll
    for (int o = 16; o; o >>= 1) s += __shfl_xor_sync(0xffffffffu, s, o);
    if ((tid & 31) == 0) red1[tid >> 5] = s;
    __syncthreads();
    float tot = 0.f;
#pragma unroll
    for (int i = 0; i < 8; i++) tot += red1[i];
    float mean = tot * (1.f / DM);

    float d0 = v0 - mean, d1 = v1 - mean, d2 = v2 - mean;
    float sq = d0 * d0 + d1 * d1 + d2 * d2;
#pragma unroll
    for (int o = 16; o; o >>= 1) sq += __shfl_xor_sync(0xffffffffu, sq, o);
    if ((tid & 31) == 0) red2[tid >> 5] = sq;
    __syncthreads();
    float vt = 0.f;
#pragma unroll
    for (int i = 0; i < 8; i++) vt += red2[i];
    float inv = rsqrtf(vt * (1.f / DM) + 1e-5f);

    float o0 = d0 * inv * w[tid]       + b[tid];
    float o1 = d1 * inv * w[tid + 256] + b[tid + 256];
    float o2 = d2 * inv * w[tid + 512] + b[tid + 512];
    if (outf) {
        outf[base + tid]       = o0;
        outf[base + tid + 256] = o1;
        outf[base + tid + 512] = o2;
    } else {
        __nv_bfloat16 h0 = __float2bfloat16(o0), h1 = __float2bfloat16(o1), h2 = __float2bfloat16(o2);
        ohi[base + tid]       = h0;  olo[base + tid]       = __float2bfloat16(o0 - __bfloat162float(h0));
        ohi[base + tid + 256] = h1;  olo[base + tid + 256] = __float2bfloat16(o1 - __bfloat162float(h1));
        ohi[base + tid + 512] = h2;  olo[base + tid + 512] = __float2bfloat16(o2 - __bfloat162float(h2));
    }
}

// ---------------- SIMT SGEMM ----------------
#define BK 16
#define SPAD 4
enum { EPI_STORE = 0, EPI_SOFTPLUS = 1 };

template <int BM, int BN, int TM, int TN, int EPI>
__device__ __forceinline__ void sgemm_body(
    const float* __restrict__ A, const float* __restrict__ B, float* __restrict__ C,
    int M, int N, int K, int lda, const float* __restrict__ bias) {
    constexpr int AE = BM * BK / 256;
    constexpr int BE = BN * BK / 256;
    __shared__ float As[BK][BM + SPAD];
    __shared__ float Bs[BK][BN + SPAD];

    int tid = threadIdx.x;
    int bm = blockIdx.y * BM;
    int bn = blockIdx.x * BN;
    int tx = tid % (BN / TN);
    int ty = tid / (BN / TN);

    float acc[TM][TN];
#pragma unroll
    for (int i = 0; i < TM; i++)
#pragma unroll
        for (int j = 0; j < TN; j++) acc[i][j] = 0.f;

    float pa[AE], pb[BE];
    auto loadA = [&](int k0) {
#pragma unroll
        for (int e = 0; e < AE; e++) {
            int i = tid + e * 256;
            int r = i / BK, kk = i % BK;
            int m = bm + r;
            pa[e] = (m < M) ? A[(long)m * lda + k0 + kk] : 0.f;
        }
    };
    auto loadB = [&](int k0) {
#pragma unroll
        for (int e = 0; e < BE; e++) {
            int i = tid + e * 256;
            int kk = i / BN, c = i % BN;
            pb[e] = B[(long)(k0 + kk) * N + bn + c];
        }
    };
    auto storeAB = [&]() {
#pragma unroll
        for (int e = 0; e < AE; e++) {
            int i = tid + e * 256;
            As[i % BK][i / BK] = pa[e];
        }
#pragma unroll
        for (int e = 0; e < BE; e++) {
            int i = tid + e * 256;
            Bs[i / BN][i % BN] = pb[e];
        }
    };

    int KT = K / BK;
    loadA(0); loadB(0);
    storeAB();
    __syncthreads();

    for (int kt = 0; kt < KT; kt++) {
        if (kt + 1 < KT) { loadA((kt + 1) * BK); loadB((kt + 1) * BK); }
#pragma unroll
        for (int kk = 0; kk < BK; kk++) {
            float a[TM], bf[TN];
#pragma unroll
            for (int i = 0; i < TM; i++) a[i] = As[kk][ty * TM + i];
#pragma unroll
            for (int j = 0; j < TN; j++) bf[j] = Bs[kk][tx * TN + j];
#pragma unroll
            for (int i = 0; i < TM; i++)
#pragma unroll
                for (int j = 0; j < TN; j++) acc[i][j] = fmaf(a[i], bf[j], acc[i][j]);
        }
        __syncthreads();
        if (kt + 1 < KT) {
            storeAB();
            __syncthreads();
        }
    }

#pragma unroll
    for (int i = 0; i < TM; i++) {
        int m = bm + ty * TM + i;
        if (m >= M) continue;
#pragma unroll
        for (int j = 0; j < TN; j++) {
            int n = bn + tx * TN + j;
            float v = acc[i][j];
            if (EPI == EPI_STORE) {
                C[(long)m * N + n] = v;
            } else {
                v += bias[m];
                C[(long)m * N + n] = (v > 20.f) ? v : __logf(1.f + __expf(v));
            }
        }
    }
}

// split-K x_proj: grid (64, 3, 4); partial[z] = xpW[:, z*384:(z+1)*384] @ xconv[z-chunk]
__global__ void __launch_bounds__(256, 2) sgemm_xproj_splitk(
    const float* __restrict__ A, const float* __restrict__ B) {
    int ks = blockIdx.z;
    sgemm_body<32, 128, 2, 8, EPI_STORE>(
        A + ks * XP_KCH, B + (size_t)ks * XP_KCH * BLTOK,
        g_xpPart + (size_t)ks * XP_PART, XP_M, BLTOK, XP_KCH, DI, nullptr);
}

// reduce partials (fixed order: deterministic) + scatter to dt / BcT / CcT
__global__ void xproj_reduce_kernel() {
    int idx = blockIdx.x * 256 + threadIdx.x;
    if (idx >= XP_PART) return;
    int m = idx >> 13, n = idx & 8191;
    float v = g_xpPart[idx];
    v += g_xpPart[idx + XP_PART];
    v += g_xpPart[idx + 2 * XP_PART];
    v += g_xpPart[idx + 3 * XP_PART];
    if (m < DTR)            g_dt[(size_t)m * BLTOK + n] = v;
    else if (m < DTR + DS)  g_BcT[(size_t)n * DS + (m - DTR)] = v;
    else                    g_CcT[(size_t)n * DS + (m - DTR - DS)] = v;
}

__global__ void __launch_bounds__(256, 2) sgemm_dtproj(
    const float* __restrict__ A, const float* __restrict__ B, float* __restrict__ C,
    const float* __restrict__ bias) {
    sgemm_body<64, 128, 4, 8, EPI_SOFTPLUS>(A, B, C, DI, BLTOK, DTR, DTR, bias);
}

// ---------------- depthwise causal conv1d + bias + SiLU ----------------
__global__ void conv_silu_kernel(const float* __restrict__ cw, const float* __restrict__ cb) {
    int idx = blockIdx.x * 256 + threadIdx.x;
    if (idx >= DI * BLTOK) return;
    int d = idx >> 13;
    int bl = idx & 8191;
    int l = bl & 4095;
    const float* xp = g_xz + (long)d * BLTOK + bl;
    float w0 = cw[d * 4], w1 = cw[d * 4 + 1], w2 = cw[d * 4 + 2], w3 = cw[d * 4 + 3];
    float acc = cb[d];
    if (l >= 3) acc = fmaf(w0, xp[-3], acc);
    if (l >= 2) acc = fmaf(w1, xp[-2], acc);
    if (l >= 1) acc = fmaf(w2, xp[-1], acc);
    acc = fmaf(w3, xp[0], acc);
    float sg = 1.f / (1.f + __expf(-acc));
    g_xconv[idx] = acc * sg;
}

// ---------------- chunked scan pass A ----------------
__global__ void scanA_kernel(const float* __restrict__ A_log) {
    int g = blockIdx.x * (blockDim.x >> 5) + (threadIdx.x >> 5);
    int lane = threadIdx.x & 31;
    int c  = g % SCH;
    int dp = (g / SCH) % (DI / 2);
    int b  = g / (SCH * (DI / 2));
    int half = lane >> 4;
    int n = lane & 15;
    int d = dp * 2 + half;

    float Acoef = -expf(A_log[d * DS + n]);

    size_t tbase = (size_t)b * L_SEQ + c * SCL;
    const float4* dp4 = (const float4*)(g_delta + (size_t)d * BLTOK + tbase);
    const float4* up4 = (const float4*)(g_xconv + (size_t)d * BLTOK + tbase);
    const float* bptr = g_BcT + tbase * DS + n;

    float P = 1.f, s = 0.f;
#pragma unroll 4
    for (int tg = 0; tg < SCL / 4; tg++) {
        float4 de4 = dp4[tg], u4 = up4[tg];
#define ASTEP(cmp, t) { float Bn = bptr[(size_t)(tg * 4 + t) * DS]; \
                        float dA = __expf(de4.cmp * Acoef); P *= dA; \
                        s = fmaf(dA, s, de4.cmp * u4.cmp * Bn); }
        ASTEP(x, 0) ASTEP(y, 1) ASTEP(z, 2) ASTEP(w, 3)
#undef ASTEP
    }
    size_t o = (((size_t)b * SCH + c) * DI + d) * DS + n;
    g_P[o] = P;
    g_Q[o] = s;
}

// ---------------- pass B ----------------
__global__ void scanB_kernel() {
    int g = blockIdx.x * (blockDim.x >> 5) + (threadIdx.x >> 5);
    int lane = threadIdx.x & 31;
    int dp = g % (DI / 2);
    int b  = g / (DI / 2);
    int half = lane >> 4;
    int n = lane & 15;
    int d = dp * 2 + half;

    float s = 0.f;
    size_t stride = (size_t)DI * DS;
    size_t o = (((size_t)b * SCH) * DI + d) * DS + n;
#pragma unroll 4
    for (int c = 0; c < SCH; c++) {
        g_S0[o] = s;
        s = fmaf(g_P[o], s, g_Q[o]);
        o += stride;
    }
}

// ---------------- pass C ----------------
__global__ void scanC_kernel(const float* __restrict__ A_log, const float* __restrict__ Dvec) {
    int g = blockIdx.x * (blockDim.x >> 5) + (threadIdx.x >> 5);
    int lane = threadIdx.x & 31;
    int c  = g % SCH;
    int dp = (g / SCH) % (DI / 2);
    int b  = g / (SCH * (DI / 2));
    int half = lane >> 4;
    int n = lane & 15;
    int d = dp * 2 + half;

    float Acoef = -expf(A_log[d * DS + n]);
    float Dv = Dvec[d];

    size_t tbase = (size_t)b * L_SEQ + c * SCL;
    const float4* dp4 = (const float4*)(g_delta + (size_t)d * BLTOK + tbase);
    const float4* up4 = (const float4*)(g_xconv + (size_t)d * BLTOK + tbase);
    const float4* zp4 = (const float4*)(g_xz + (size_t)(DI + d) * BLTOK + tbase);
    const float* bptr = g_BcT + tbase * DS + n;
    const float* cptr = g_CcT + tbase * DS + n;
    float* yptr = g_y + (size_t)d * BLTOK + tbase;

    float s = g_S0[(((size_t)b * SCH + c) * DI + d) * DS + n];
#pragma unroll 2
    for (int tg = 0; tg < SCL / 4; tg++) {
        float4 de4 = dp4[tg], u4 = up4[tg], z4 = zp4[tg];
#define CSTEP(cmp, t) { int tt = tg * 4 + t; \
                        float Bn = bptr[(size_t)tt * DS]; \
                        float Cn = cptr[(size_t)tt * DS]; \
                        float dA = __expf(de4.cmp * Acoef); \
                        s = fmaf(dA, s, de4.cmp * u4.cmp * Bn); \
                        float p = s * Cn; \
                        p += __shfl_xor_sync(0xffffffffu, p, 8, 16); \
                        p += __shfl_xor_sync(0xffffffffu, p, 4, 16); \
                        p += __shfl_xor_sync(0xffffffffu, p, 2, 16); \
                        p += __shfl_xor_sync(0xffffffffu, p, 1, 16); \
                        float yv = fmaf(Dv, u4.cmp, p); \
                        float sg = 1.f / (1.f + __expf(-z4.cmp)); \
                        yv *= z4.cmp * sg; \
                        if (n == 0) yptr[tt] = yv; }
        CSTEP(x, 0) CSTEP(y, 1) CSTEP(z, 2) CSTEP(w, 3)
#undef CSTEP
    }
}

// ---------------- host launcher ----------------
extern "C" void kernel_launch(void* const* d_in, const int* in_sizes, int n_in,
                              void* d_out, int out_size) {
    const float* x     = (const float*)d_in[0];
    const float* embW  = (const float*)d_in[1];
    const float* embB  = (const float*)d_in[2];
    const float* normw = (const float*)d_in[3];
    const float* normb = (const float*)d_in[4];
    const float* inW   = (const float*)d_in[5];
    const float* convw = (const float*)d_in[6];
    const float* convb = (const float*)d_in[7];
    const float* xpW   = (const float*)d_in[8];
    const float* dtW   = (const float*)d_in[9];
    const float* dtb   = (const float*)d_in[10];
    const float* Alog  = (const float*)d_in[11];
    const float* Dv    = (const float*)d_in[12];
    const float* outW  = (const float*)d_in[13];
    const float* nfw   = (const float*)d_in[14];
    const float* nfb   = (const float*)d_in[15];
    float* out = (float*)d_out;

    float *h, *res, *xz, *xconv, *dt, *delta, *y;
    __nv_bfloat16 *winh, *winl, *wouth, *woutl, *hnh, *hnl, *yh, *yl;
    cudaGetSymbolAddress((void**)&h,     g_h);
    cudaGetSymbolAddress((void**)&res,   g_res);
    cudaGetSymbolAddress((void**)&xz,    g_xz);
    cudaGetSymbolAddress((void**)&xconv, g_xconv);
    cudaGetSymbolAddress((void**)&dt,    g_dt);
    cudaGetSymbolAddress((void**)&delta, g_delta);
    cudaGetSymbolAddress((void**)&y,     g_y);
    cudaGetSymbolAddress((void**)&winh,  g_WinHi);
    cudaGetSymbolAddress((void**)&winl,  g_WinLo);
    cudaGetSymbolAddress((void**)&wouth, g_WoutHi);
    cudaGetSymbolAddress((void**)&woutl, g_WoutLo);
    cudaGetSymbolAddress((void**)&hnh,   g_hnHi);
    cudaGetSymbolAddress((void**)&hnl,   g_hnLo);
    cudaGetSymbolAddress((void**)&yh,    g_yHi);
    cudaGetSymbolAddress((void**)&yl,    g_yLo);

    cudaFuncSetAttribute(mma_gemm_a, cudaFuncAttributeMaxDynamicSharedMemorySize, MMASMEM);
    cudaFuncSetAttribute(mma_gemm_b, cudaFuncAttributeMaxDynamicSharedMemorySize, MMASMEM);

    const int SCAN_WARPS = NB * (DI / 2) * SCH;
    const int SCANB_WARPS = NB * (DI / 2);

    embed_kernel<<<BLTOK, 256>>>(x, embW, embB);
    cvt_all_kernel<<<(CVT_TOTAL + 255) / 256, 256>>>(inW, outW);

    for (int lyr = 0; lyr < NLAYER; lyr++) {
        resln_kernel<<<BLTOK, 256>>>(h, res, nullptr, hnh, hnl,
                                     normw + lyr * DM, normb + lyr * DM, lyr > 0 ? 1 : 0);
        mma_gemm_a<<<dim3(64, 24), 256, MMASMEM>>>(                       // slot 3 control
            winh + (size_t)lyr * NIN_W, winl + (size_t)lyr * NIN_W, hnh, hnl, xz, DM, BLTOK);
        conv_silu_kernel<<<(DI * BLTOK + 255) / 256, 256>>>(convw + lyr * DI * 4, convb + lyr * DI);
        sgemm_xproj_splitk<<<dim3(64, 3, XP_KSPL), 256>>>(
            xpW + (long)lyr * XP_M * DI, xconv);
        xproj_reduce_kernel<<<(XP_PART + 255) / 256, 256>>>();
        sgemm_dtproj<<<dim3(64, 24), 256>>>(
            dtW + (long)lyr * DI * DTR, dt, delta, dtb + lyr * DI);
        scanA_kernel<<<SCAN_WARPS / 4, 128>>>(Alog + (long)lyr * DI * DS);
        scanB_kernel<<<SCANB_WARPS / 4, 128>>>();
        scanC_kernel<<<SCAN_WARPS / 4, 128>>>(Alog + (long)lyr * DI * DS, Dv + lyr * DI);
        tcvt_kernel<<<dim3(BLTOK / 32, DI / 32), 256>>>(y, yh, yl);
        mma_gemm_b<<<dim3(64, 6), 256, MMASMEM>>>(
            wouth + (size_t)lyr * NOUT_W, woutl + (size_t)lyr * NOUT_W, yh, yl, h, DI, DM);
    }

    resln_kernel<<<BLTOK, 256>>>(h, res, out, nullptr, nullptr, nfw, nfb, 1);
}

// round 17
// speedup vs baseline: 1.2603x; 1.0207x over previous
#include <cuda_runtime.h>
#include <cuda_bf16.h>
#include <math.h>
#include <stdint.h>

#define L_SEQ  4096
#define NB     2
#define BLTOK  8192
#define DM     768
#define DI     1536
#define DS     16
#define DTR    48
#define NLAYER 4

#define NIN_W  (2 * DI * DM)
#define NOUT_W (DM * DI)

#define SCH 64
#define SCL 64

#define XP_M     80
#define XP_KSPL  4
#define XP_KCH   (DI / XP_KSPL)      // 384
#define XP_PART  (XP_M * BLTOK)

// ---------------- scratch ----------------
__device__ float g_h    [BLTOK * DM];
__device__ float g_res  [BLTOK * DM];
__device__ float g_xz   [2 * DI * BLTOK];   // (channel, token)
__device__ float g_xconv[DI * BLTOK];
__device__ float g_BcT  [BLTOK * DS];       // (token, n)
__device__ float g_CcT  [BLTOK * DS];
__device__ float g_delta[DI * BLTOK];
__device__ float g_y    [DI * BLTOK];       // (channel, token)
__device__ float g_xpPart[XP_KSPL * XP_PART];

__device__ float g_P [NB * SCH * DI * DS];
__device__ float g_Q [NB * SCH * DI * DS];
__device__ float g_S0[NB * SCH * DI * DS];

__device__ __nv_bfloat16 g_WinHi[NLAYER * NIN_W],  g_WinLo[NLAYER * NIN_W];
__device__ __nv_bfloat16 g_WoutHi[NLAYER * NOUT_W], g_WoutLo[NLAYER * NOUT_W];
__device__ __nv_bfloat16 g_hnHi[BLTOK * DM],  g_hnLo[BLTOK * DM];
__device__ __nv_bfloat16 g_yHi[BLTOK * DI],   g_yLo[BLTOK * DI];

// ---------------- helpers ----------------
__device__ __forceinline__ uint32_t smem_u32(const void* p) {
    uint32_t a;
    asm("{ .reg .u64 t; cvta.to.shared.u64 t, %1; cvt.u32.u64 %0, t; }" : "=r"(a) : "l"(p));
    return a;
}
#define LDSM_X4(r0, r1, r2, r3, a) \
    asm volatile("ldmatrix.sync.aligned.m8n8.x4.shared.b16 {%0,%1,%2,%3}, [%4];" \
                 : "=r"(r0), "=r"(r1), "=r"(r2), "=r"(r3) : "r"(a))
#define MMA_BF16(c, a0, a1, a2, a3, b0, b1) \
    asm volatile("mma.sync.aligned.m16n8k16.row.col.f32.bf16.bf16.f32 " \
                 "{%0,%1,%2,%3}, {%4,%5,%6,%7}, {%8,%9}, {%0,%1,%2,%3};" \
                 : "+f"((c)[0]), "+f"((c)[1]), "+f"((c)[2]), "+f"((c)[3]) \
                 : "r"(a0), "r"(a1), "r"(a2), "r"(a3), "r"(b0), "r"(b1))
#define CP_A16(dst, src) \
    asm volatile("cp.async.cg.shared.global [%0], [%1], 16;" :: "r"(dst), "l"(src))
#define CP_COMMIT()  asm volatile("cp.async.commit_group;")
#define CP_WAIT(n)   asm volatile("cp.async.wait_group %0;" :: "n"(n))

// ---------------- mma.sync 3xBF16 GEMM ----------------
#define TILE_B  10240
#define STAGE_B 40960
#define EPI_STRIDE 130
#define MMASMEM 81920

template <int LAYOUT>
__device__ __forceinline__ void mma_gemm_body(
    char* dsm,
    const __nv_bfloat16* __restrict__ Ahi, const __nv_bfloat16* __restrict__ Alo,
    const __nv_bfloat16* __restrict__ Bhi, const __nv_bfloat16* __restrict__ Blo,
    float* __restrict__ C, int K, int ldc) {
    const int tid = threadIdx.x;
    const int wid = tid >> 5;
    const int lane = tid & 31;
    const int bm = blockIdx.y * 128;
    const int bn = blockIdx.x * 128;
    const int wm = (wid >> 2) * 64;
    const int wn = (wid & 3) * 32;

    const uint32_t sb = smem_u32(dsm);

    uint32_t so[2];
    size_t offA[2], offB[2];
#pragma unroll
    for (int j = 0; j < 2; j++) {
        int v = tid + j * 256;
        int row = v >> 2, c = v & 3;
        so[j] = row * 80 + c * 16;
        offA[j] = (size_t)(bm + row) * K + c * 8;
        offB[j] = (size_t)(bn + row) * K + c * 8;
    }

    uint32_t aoff[4], boff[2];
    {
        int g = lane >> 3, r = lane & 7;
#pragma unroll
        for (int mt = 0; mt < 4; mt++) {
            int row = wm + mt * 16 + (g & 1) * 8 + r;
            aoff[mt] = row * 80 + (g >> 1) * 16;
        }
#pragma unroll
        for (int p = 0; p < 2; p++) {
            int row = wn + p * 16 + (g >> 1) * 8 + r;
            boff[p] = row * 80 + (g & 1) * 16;
        }
    }

    const int KT = K >> 5;

    auto issue = [&](int kc, int stg) {
        int k0 = kc << 5;
        uint32_t base = sb + stg * STAGE_B;
#pragma unroll
        for (int j = 0; j < 2; j++) {
            uint32_t d = base + so[j];
            CP_A16(d,              Ahi + offA[j] + k0);
            CP_A16(d + TILE_B,     Alo + offA[j] + k0);
            CP_A16(d + 2 * TILE_B, Bhi + offB[j] + k0);
            CP_A16(d + 3 * TILE_B, Blo + offB[j] + k0);
        }
        CP_COMMIT();
    };

    float acc[4][4][4];
#pragma unroll
    for (int mt = 0; mt < 4; mt++)
#pragma unroll
        for (int nt = 0; nt < 4; nt++)
#pragma unroll
            for (int e = 0; e < 4; e++) acc[mt][nt][e] = 0.f;

    issue(0, 0);
    if (KT > 1) issue(1, 1);

    for (int kc = 0; kc < KT; kc++) {
        if (kc + 1 < KT) CP_WAIT(1); else CP_WAIT(0);
        __syncthreads();
        uint32_t base = sb + (kc & 1) * STAGE_B;
        uint32_t sAh = base, sAl = base + TILE_B, sBh = base + 2 * TILE_B, sBl = base + 3 * TILE_B;
#pragma unroll
        for (int ks = 0; ks < 2; ks++) {
            uint32_t kb = ks * 32;
            uint32_t bh[2][4], bl[2][4];
#pragma unroll
            for (int p = 0; p < 2; p++) {
                LDSM_X4(bh[p][0], bh[p][1], bh[p][2], bh[p][3], sBh + boff[p] + kb);
                LDSM_X4(bl[p][0], bl[p][1], bl[p][2], bl[p][3], sBl + boff[p] + kb);
            }
#pragma unroll
            for (int mt = 0; mt < 4; mt++) {
                uint32_t ah[4], al[4];
                LDSM_X4(ah[0], ah[1], ah[2], ah[3], sAh + aoff[mt] + kb);
                LDSM_X4(al[0], al[1], al[2], al[3], sAl + aoff[mt] + kb);
#pragma unroll
                for (int nt = 0; nt < 4; nt++) {
                    int p = nt >> 1, h = (nt & 1) * 2;
                    MMA_BF16(acc[mt][nt], ah[0], ah[1], ah[2], ah[3], bh[p][h], bh[p][h + 1]);
                    MMA_BF16(acc[mt][nt], ah[0], ah[1], ah[2], ah[3], bl[p][h], bl[p][h + 1]);
                    MMA_BF16(acc[mt][nt], al[0], al[1], al[2], al[3], bh[p][h], bh[p][h + 1]);
                }
            }
        }
        __syncthreads();
        if (kc + 2 < KT) issue(kc + 2, kc & 1);
    }

    float* st = (float*)dsm;
    {
        int mr = lane >> 2;
        int nc = (lane & 3) * 2;
#pragma unroll
        for (int mt = 0; mt < 4; mt++) {
#pragma unroll
            for (int nt = 0; nt < 4; nt++) {
                int m0 = wm + mt * 16 + mr;
                int n0 = wn + nt * 8 + nc;
                *(float2*)(st + m0 * EPI_STRIDE + n0) = make_float2(acc[mt][nt][0], acc[mt][nt][1]);
                *(float2*)(st + (m0 + 8) * EPI_STRIDE + n0) = make_float2(acc[mt][nt][2], acc[mt][nt][3]);
            }
        }
    }
    __syncthreads();
    if (LAYOUT == 0) {
        for (int idx = tid; idx < 16384; idx += 256) {
            int r = idx >> 7, c = idx & 127;
            C[(size_t)(bm + r) * ldc + bn + c] = st[r * EPI_STRIDE + c];
        }
    } else {
        for (int idx = tid; idx < 16384; idx += 256) {
            int n = idx >> 7, m = idx & 127;
            C[(size_t)(bn + n) * ldc + bm + m] = st[m * EPI_STRIDE + n];
        }
    }
}

__global__ void __launch_bounds__(256, 2) mma_gemm_a(
    const __nv_bfloat16* __restrict__ Ahi, const __nv_bfloat16* __restrict__ Alo,
    const __nv_bfloat16* __restrict__ Bhi, const __nv_bfloat16* __restrict__ Blo,
    float* __restrict__ C, int K, int ldc) {
    extern __shared__ char dsm[];
    mma_gemm_body<0>(dsm, Ahi, Alo, Bhi, Blo, C, K, ldc);
}
__global__ void __launch_bounds__(256, 2) mma_gemm_b(
    const __nv_bfloat16* __restrict__ Ahi, const __nv_bfloat16* __restrict__ Alo,
    const __nv_bfloat16* __restrict__ Bhi, const __nv_bfloat16* __restrict__ Blo,
    float* __restrict__ C, int K, int ldc) {
    extern __shared__ char dsm[];
    mma_gemm_body<1>(dsm, Ahi, Alo, Bhi, Blo, C, K, ldc);
}

// ---------------- all-layer weight fp32 -> bf16 hi/lo ----------------
#define CVT_TOTAL (NLAYER * (NIN_W + NOUT_W))
__global__ void cvt_all_kernel(const float* __restrict__ inW, const float* __restrict__ outW) {
    int i = blockIdx.x * 256 + threadIdx.x;
    if (i >= CVT_TOTAL) return;
    float v;
    __nv_bfloat16 *hi, *lo;
    if (i < NLAYER * NIN_W) {
        v = inW[i];
        hi = g_WinHi + i; lo = g_WinLo + i;
    } else {
        int j = i - NLAYER * NIN_W;
        v = outW[j];
        hi = g_WoutHi + j; lo = g_WoutLo + j;
    }
    __nv_bfloat16 h = __float2bfloat16(v);
    *hi = h;
    *lo = __float2bfloat16(v - __bfloat162float(h));
}

// ---------------- transpose (d,tok)->(tok,d) + bf16 hi/lo ----------------
__global__ void tcvt_kernel(const float* __restrict__ src, __nv_bfloat16* __restrict__ hi,
                            __nv_bfloat16* __restrict__ lo) {
    __shared__ float t[32][33];
    int tx = threadIdx.x & 31, ty = threadIdx.x >> 5;
    int tok0 = blockIdx.x * 32, d0 = blockIdx.y * 32;
#pragma unroll
    for (int i = 0; i < 4; i++) {
        int d = d0 + ty + i * 8;
        t[ty + i * 8][tx] = src[(size_t)d * BLTOK + tok0 + tx];
    }
    __syncthreads();
#pragma unroll
    for (int i = 0; i < 4; i++) {
        int tok = tok0 + ty + i * 8;
        float v = t[tx][ty + i * 8];
        __nv_bfloat16 h = __float2bfloat16(v);
        size_t o = (size_t)tok * DI + d0 + tx;
        hi[o] = h;
        lo[o] = __float2bfloat16(v - __bfloat162float(h));
    }
}

// ---------------- embed ----------------
__global__ void embed_kernel(const float* __restrict__ x, const float* __restrict__ W,
                             const float* __restrict__ bias) {
    __shared__ float xs[64];
    int tok = blockIdx.x;
    int b = tok >> 12, l = tok & 4095;
    int tid = threadIdx.x;
    if (tid < 64) xs[tid] = x[(b * 64 + tid) * L_SEQ + l];
    __syncthreads();
    for (int e = tid; e < DM; e += 256) {
        const float* w = W + e * 64;
        float acc = bias[e];
#pragma unroll 16
        for (int i = 0; i < 64; i++) acc = fmaf(w[i], xs[i], acc);
        g_h[tok * DM + e] = acc;
    }
}

// ---------------- fused residual + layernorm ----------------
__global__ void resln_kernel(const float* __restrict__ src, float* __restrict__ res,
                             float* __restrict__ outf, __nv_bfloat16* __restrict__ ohi,
                             __nv_bfloat16* __restrict__ olo,
                             const float* __restrict__ w, const float* __restrict__ b, int add) {
    __shared__ float red1[8], red2[8];
    int base = blockIdx.x * DM;
    int tid = threadIdx.x;
    float v0 = src[base + tid];
    float v1 = src[base + tid + 256];
    float v2 = src[base + tid + 512];
    if (add) {
        v0 += res[base + tid];
        v1 += res[base + tid + 256];
        v2 += res[base + tid + 512];
    }
    res[base + tid]       = v0;
    res[base + tid + 256] = v1;
    res[base + tid + 512] = v2;

    float s = v0 + v1 + v2;
#pragma unroll
    for (int o = 16; o; o >>= 1) s += __shfl_xor_sync(0xffffffffu, s, o);
    if ((tid & 31) == 0) red1[tid >> 5] = s;
    __syncthreads();
    float tot = 0.f;
#pragma unroll
    for (int i = 0; i < 8; i++) tot += red1[i];
    float mean = tot * (1.f / DM);

    float d0 = v0 - mean, d1 = v1 - mean, d2 = v2 - mean;
    float sq = d0 * d0 + d1 * d1 + d2 * d2;
#pragma unroll
    for (int o = 16; o; o >>= 1) sq += __shfl_xor_sync(0xffffffffu, sq, o);
    if ((tid & 31) == 0) red2[tid >> 5] = sq;
    __syncthreads();
    float vt = 0.f;
#pragma unroll
    for (int i = 0; i < 8; i++) vt += red2[i];
    float inv = rsqrtf(vt * (1.f / DM) + 1e-5f);

    float o0 = d0 * inv * w[tid]       + b[tid];
    float o1 = d1 * inv * w[tid + 256] + b[tid + 256];
    float o2 = d2 * inv * w[tid + 512] + b[tid + 512];
    if (outf) {
        outf[base + tid]       = o0;
        outf[base + tid + 256] = o1;
        outf[base + tid + 512] = o2;
    } else {
        __nv_bfloat16 h0 = __float2bfloat16(o0), h1 = __float2bfloat16(o1), h2 = __float2bfloat16(o2);
        ohi[base + tid]       = h0;  olo[base + tid]       = __float2bfloat16(o0 - __bfloat162float(h0));
        ohi[base + tid + 256] = h1;  olo[base + tid + 256] = __float2bfloat16(o1 - __bfloat162float(h1));
        ohi[base + tid + 512] = h2;  olo[base + tid + 512] = __float2bfloat16(o2 - __bfloat162float(h2));
    }
}

// ---------------- SIMT SGEMM ----------------
#define BK 16
#define SPAD 4

// split-K x_proj partial: 32x128 tile, K = 384 chunk
__global__ void __launch_bounds__(256, 2) sgemm_xproj_splitk(
    const float* __restrict__ A, const float* __restrict__ B) {
    constexpr int BM = 32, BN = 128, TM = 2, TN = 8;
    constexpr int AE = BM * BK / 256;
    constexpr int BE = BN * BK / 256;
    __shared__ float As[BK][BM + SPAD];
    __shared__ float Bs[BK][BN + SPAD];

    int ks = blockIdx.z;
    const float* Ab = A + ks * XP_KCH;
    const float* Bb = B + (size_t)ks * XP_KCH * BLTOK;
    float* Cb = g_xpPart + (size_t)ks * XP_PART;

    int tid = threadIdx.x;
    int bm = blockIdx.y * BM;
    int bn = blockIdx.x * BN;
    int tx = tid % (BN / TN);
    int ty = tid / (BN / TN);

    float acc[TM][TN];
#pragma unroll
    for (int i = 0; i < TM; i++)
#pragma unroll
        for (int j = 0; j < TN; j++) acc[i][j] = 0.f;

    float pa[AE], pb[BE];
    auto loadA = [&](int k0) {
#pragma unroll
        for (int e = 0; e < AE; e++) {
            int i = tid + e * 256;
            int r = i / BK, kk = i % BK;
            int m = bm + r;
            pa[e] = (m < XP_M) ? Ab[(long)m * DI + k0 + kk] : 0.f;
        }
    };
    auto loadB = [&](int k0) {
#pragma unroll
        for (int e = 0; e < BE; e++) {
            int i = tid + e * 256;
            int kk = i / BN, c = i % BN;
            pb[e] = Bb[(long)(k0 + kk) * BLTOK + bn + c];
        }
    };
    auto storeAB = [&]() {
#pragma unroll
        for (int e = 0; e < AE; e++) {
            int i = tid + e * 256;
            As[i % BK][i / BK] = pa[e];
        }
#pragma unroll
        for (int e = 0; e < BE; e++) {
            int i = tid + e * 256;
            Bs[i / BN][i % BN] = pb[e];
        }
    };

    int KT = XP_KCH / BK;
    loadA(0); loadB(0);
    storeAB();
    __syncthreads();
    for (int kt = 0; kt < KT; kt++) {
        if (kt + 1 < KT) { loadA((kt + 1) * BK); loadB((kt + 1) * BK); }
#pragma unroll
        for (int kk = 0; kk < BK; kk++) {
            float a[TM], bf[TN];
#pragma unroll
            for (int i = 0; i < TM; i++) a[i] = As[kk][ty * TM + i];
#pragma unroll
            for (int j = 0; j < TN; j++) bf[j] = Bs[kk][tx * TN + j];
#pragma unroll
            for (int i = 0; i < TM; i++)
#pragma unroll
                for (int j = 0; j < TN; j++) acc[i][j] = fmaf(a[i], bf[j], acc[i][j]);
        }
        __syncthreads();
        if (kt + 1 < KT) {
            storeAB();
            __syncthreads();
        }
    }
#pragma unroll
    for (int i = 0; i < TM; i++) {
        int m = bm + ty * TM + i;
        if (m >= XP_M) continue;
#pragma unroll
        for (int j = 0; j < TN; j++)
            Cb[(long)m * BLTOK + bn + tx * TN + j] = acc[i][j];
    }
}

// reduce only B/C rows (m in [48,80)), fixed z-order (deterministic)
__global__ void xproj_reduce_kernel() {
    int idx = blockIdx.x * 256 + threadIdx.x;
    if (idx >= 2 * DS * BLTOK) return;
    int m2 = idx >> 13, n = idx & 8191;
    size_t o = (size_t)(DTR + m2) * BLTOK + n;
    float v = g_xpPart[o];
    v += g_xpPart[o + XP_PART];
    v += g_xpPart[o + 2 * XP_PART];
    v += g_xpPart[o + 3 * XP_PART];
    if (m2 < DS) g_BcT[(size_t)n * DS + m2] = v;
    else         g_CcT[(size_t)n * DS + (m2 - DS)] = v;
}

// dt_proj: B rows (m<48) summed from the 4 partials inline, + softplus
__global__ void __launch_bounds__(256, 2) sgemm_dtproj(
    const float* __restrict__ A, float* __restrict__ C,
    const float* __restrict__ bias) {
    constexpr int BM = 64, BN = 128, TM = 4, TN = 8;
    constexpr int AE = BM * BK / 256;
    constexpr int BE = BN * BK / 256;
    __shared__ float As[BK][BM + SPAD];
    __shared__ float Bs[BK][BN + SPAD];

    int tid = threadIdx.x;
    int bm = blockIdx.y * BM;
    int bn = blockIdx.x * BN;
    int tx = tid % (BN / TN);
    int ty = tid / (BN / TN);

    float acc[TM][TN];
#pragma unroll
    for (int i = 0; i < TM; i++)
#pragma unroll
        for (int j = 0; j < TN; j++) acc[i][j] = 0.f;

    float pa[AE], pb[BE];
    auto loadA = [&](int k0) {
#pragma unroll
        for (int e = 0; e < AE; e++) {
            int i = tid + e * 256;
            int r = i / BK, kk = i % BK;
            pa[e] = A[(long)(bm + r) * DTR + k0 + kk];
        }
    };
    auto loadB = [&](int k0) {
#pragma unroll
        for (int e = 0; e < BE; e++) {
            int i = tid + e * 256;
            int kk = i / BN, c = i % BN;
            size_t o = (size_t)(k0 + kk) * BLTOK + bn + c;
            float v = g_xpPart[o];
            v += g_xpPart[o + XP_PART];
            v += g_xpPart[o + 2 * XP_PART];
            v += g_xpPart[o + 3 * XP_PART];
            pb[e] = v;
        }
    };
    auto storeAB = [&]() {
#pragma unroll
        for (int e = 0; e < AE; e++) {
            int i = tid + e * 256;
            As[i % BK][i / BK] = pa[e];
        }
#pragma unroll
        for (int e = 0; e < BE; e++) {
            int i = tid + e * 256;
            Bs[i / BN][i % BN] = pb[e];
        }
    };

    int KT = DTR / BK;
    loadA(0); loadB(0);
    storeAB();
    __syncthreads();
    for (int kt = 0; kt < KT; kt++) {
        if (kt + 1 < KT) { loadA((kt + 1) * BK); loadB((kt + 1) * BK); }
#pragma unroll
        for (int kk = 0; kk < BK; kk++) {
            float a[TM], bf[TN];
#pragma unroll
            for (int i = 0; i < TM; i++) a[i] = As[kk][ty * TM + i];
#pragma unroll
            for (int j = 0; j < TN; j++) bf[j] = Bs[kk][tx * TN + j];
#pragma unroll
            for (int i = 0; i < TM; i++)
#pragma unroll
                for (int j = 0; j < TN; j++) acc[i][j] = fmaf(a[i], bf[j], acc[i][j]);
        }
        __syncthreads();
        if (kt + 1 < KT) {
            storeAB();
            __syncthreads();
        }
    }
#pragma unroll
    for (int i = 0; i < TM; i++) {
        int m = bm + ty * TM + i;
#pragma unroll
        for (int j = 0; j < TN; j++) {
            float v = acc[i][j] + bias[m];
            C[(long)m * BLTOK + bn + tx * TN + j] = (v > 20.f) ? v : __logf(1.f + __expf(v));
        }
    }
}

// ---------------- depthwise causal conv1d + bias + SiLU (float4) ----------------
__global__ void conv_silu_kernel(const float* __restrict__ cw, const float* __restrict__ cb) {
    int v = blockIdx.x * 256 + threadIdx.x;
    if (v >= DI * BLTOK / 4) return;
    int d = v >> 11;            // / 2048 float4s per channel row
    int blv = v & 2047;
    const float4* xp = (const float4*)(g_xz + (size_t)d * BLTOK) + blv;
    float4 cur = xp[0];
    float4 prev = ((blv & 1023) == 0) ? make_float4(0.f, 0.f, 0.f, 0.f) : xp[-1];
    float w0 = cw[d * 4], w1 = cw[d * 4 + 1], w2 = cw[d * 4 + 2], w3 = cw[d * 4 + 3];
    float bv = cb[d];
    float win[8] = {prev.x, prev.y, prev.z, prev.w, cur.x, cur.y, cur.z, cur.w};
    float4 o;
#pragma unroll
    for (int i = 0; i < 4; i++) {
        float a = bv;
        a = fmaf(w0, win[i + 1], a);
        a = fmaf(w1, win[i + 2], a);
        a = fmaf(w2, win[i + 3], a);
        a = fmaf(w3, win[i + 4], a);
        float sg = 1.f / (1.f + __expf(-a));
        ((float*)&o)[i] = a * sg;
    }
    ((float4*)(g_xconv + (size_t)d * BLTOK))[blv] = o;
}

// ---------------- chunked scan pass A ----------------
__global__ void scanA_kernel(const float* __restrict__ A_log) {
    int g = blockIdx.x * (blockDim.x >> 5) + (threadIdx.x >> 5);
    int lane = threadIdx.x & 31;
    int c  = g % SCH;
    int dp = (g / SCH) % (DI / 2);
    int b  = g / (SCH * (DI / 2));
    int half = lane >> 4;
    int n = lane & 15;
    int d = dp * 2 + half;

    float Acoef = -expf(A_log[d * DS + n]);

    size_t tbase = (size_t)b * L_SEQ + c * SCL;
    const float4* dp4 = (const float4*)(g_delta + (size_t)d * BLTOK + tbase);
    const float4* up4 = (const float4*)(g_xconv + (size_t)d * BLTOK + tbase);
    const float* bptr = g_BcT + tbase * DS + n;

    float P = 1.f, s = 0.f;
#pragma unroll 4
    for (int tg = 0; tg < SCL / 4; tg++) {
        float4 de4 = dp4[tg], u4 = up4[tg];
#define ASTEP(cmp, t) { float Bn = bptr[(size_t)(tg * 4 + t) * DS]; \
                        float dA = __expf(de4.cmp * Acoef); P *= dA; \
                        s = fmaf(dA, s, de4.cmp * u4.cmp * Bn); }
        ASTEP(x, 0) ASTEP(y, 1) ASTEP(z, 2) ASTEP(w, 3)
#undef ASTEP
    }
    size_t o = (((size_t)b * SCH + c) * DI + d) * DS + n;
    g_P[o] = P;
    g_Q[o] = s;
}

// ---------------- pass B (1-ahead prefetch) ----------------
__global__ void scanB_kernel() {
    int g = blockIdx.x * (blockDim.x >> 5) + (threadIdx.x >> 5);
    int lane = threadIdx.x & 31;
    int dp = g % (DI / 2);
    int b  = g / (DI / 2);
    int half = lane >> 4;
    int n = lane & 15;
    int d = dp * 2 + half;

    float s = 0.f;
    size_t stride = (size_t)DI * DS;
    size_t o = (((size_t)b * SCH) * DI + d) * DS + n;
    float Pc = g_P[o], Qc = g_Q[o];
#pragma unroll 4
    for (int c = 0; c < SCH; c++) {
        size_t on = o + stride;
        float Pn = 0.f, Qn = 0.f;
        if (c + 1 < SCH) { Pn = g_P[on]; Qn = g_Q[on]; }
        g_S0[o] = s;
        s = fmaf(Pc, s, Qc);
        Pc = Pn; Qc = Qn; o = on;
    }
}

// ---------------- pass C ----------------
__global__ void scanC_kernel(const float* __restrict__ A_log, const float* __restrict__ Dvec) {
    int g = blockIdx.x * (blockDim.x >> 5) + (threadIdx.x >> 5);
    int lane = threadIdx.x & 31;
    int c  = g % SCH;
    int dp = (g / SCH) % (DI / 2);
    int b  = g / (SCH * (DI / 2));
    int half = lane >> 4;
    int n = lane & 15;
    int d = dp * 2 + half;

    float Acoef = -expf(A_log[d * DS + n]);
    float Dv = Dvec[d];

    size_t tbase = (size_t)b * L_SEQ + c * SCL;
    const float4* dp4 = (const float4*)(g_delta + (size_t)d * BLTOK + tbase);
    const float4* up4 = (const float4*)(g_xconv + (size_t)d * BLTOK + tbase);
    const float4* zp4 = (const float4*)(g_xz + (size_t)(DI + d) * BLTOK + tbase);
    const float* bptr = g_BcT + tbase * DS + n;
    const float* cptr = g_CcT + tbase * DS + n;
    float* yptr = g_y + (size_t)d * BLTOK + tbase;

    float s = g_S0[(((size_t)b * SCH + c) * DI + d) * DS + n];
#pragma unroll 2
    for (int tg = 0; tg < SCL / 4; tg++) {
        float4 de4 = dp4[tg], u4 = up4[tg], z4 = zp4[tg];
#define CSTEP(cmp, t) { int tt = tg * 4 + t; \
                        float Bn = bptr[(size_t)tt * DS]; \
                        float Cn = cptr[(size_t)tt * DS]; \
                        float dA = __expf(de4.cmp * Acoef); \
                        s = fmaf(dA, s, de4.cmp * u4.cmp * Bn); \
                        float p = s * Cn; \
                        p += __shfl_xor_sync(0xffffffffu, p, 8, 16); \
                        p += __shfl_xor_sync(0xffffffffu, p, 4, 16); \
                        p += __shfl_xor_sync(0xffffffffu, p, 2, 16); \
                        p += __shfl_xor_sync(0xffffffffu, p, 1, 16); \
                        float yv = fmaf(Dv, u4.cmp, p); \
                        float sg = 1.f / (1.f + __expf(-z4.cmp)); \
                        yv *= z4.cmp * sg; \
                        if (n == 0) yptr[tt] = yv; }
        CSTEP(x, 0) CSTEP(y, 1) CSTEP(z, 2) CSTEP(w, 3)
#undef CSTEP
    }
}

// ---------------- host launcher ----------------
extern "C" void kernel_launch(void* const* d_in, const int* in_sizes, int n_in,
                              void* d_out, int out_size) {
    const float* x     = (const float*)d_in[0];
    const float* embW  = (const float*)d_in[1];
    const float* embB  = (const float*)d_in[2];
    const float* normw = (const float*)d_in[3];
    const float* normb = (const float*)d_in[4];
    const float* inW   = (const float*)d_in[5];
    const float* convw = (const float*)d_in[6];
    const float* convb = (const float*)d_in[7];
    const float* xpW   = (const float*)d_in[8];
    const float* dtW   = (const float*)d_in[9];
    const float* dtb   = (const float*)d_in[10];
    const float* Alog  = (const float*)d_in[11];
    const float* Dv    = (const float*)d_in[12];
    const float* outW  = (const float*)d_in[13];
    const float* nfw   = (const float*)d_in[14];
    const float* nfb   = (const float*)d_in[15];
    float* out = (float*)d_out;

    float *h, *res, *xz, *xconv, *delta, *y;
    __nv_bfloat16 *winh, *winl, *wouth, *woutl, *hnh, *hnl, *yh, *yl;
    cudaGetSymbolAddress((void**)&h,     g_h);
    cudaGetSymbolAddress((void**)&res,   g_res);
    cudaGetSymbolAddress((void**)&xz,    g_xz);
    cudaGetSymbolAddress((void**)&xconv, g_xconv);
    cudaGetSymbolAddress((void**)&delta, g_delta);
    cudaGetSymbolAddress((void**)&y,     g_y);
    cudaGetSymbolAddress((void**)&winh,  g_WinHi);
    cudaGetSymbolAddress((void**)&winl,  g_WinLo);
    cudaGetSymbolAddress((void**)&wouth, g_WoutHi);
    cudaGetSymbolAddress((void**)&woutl, g_WoutLo);
    cudaGetSymbolAddress((void**)&hnh,   g_hnHi);
    cudaGetSymbolAddress((void**)&hnl,   g_hnLo);
    cudaGetSymbolAddress((void**)&yh,    g_yHi);
    cudaGetSymbolAddress((void**)&yl,    g_yLo);

    cudaFuncSetAttribute(mma_gemm_a, cudaFuncAttributeMaxDynamicSharedMemorySize, MMASMEM);
    cudaFuncSetAttribute(mma_gemm_b, cudaFuncAttributeMaxDynamicSharedMemorySize, MMASMEM);

    const int SCAN_WARPS = NB * (DI / 2) * SCH;
    const int SCANB_WARPS = NB * (DI / 2);

    embed_kernel<<<BLTOK, 256>>>(x, embW, embB);
    cvt_all_kernel<<<(CVT_TOTAL + 255) / 256, 256>>>(inW, outW);

    for (int lyr = 0; lyr < NLAYER; lyr++) {
        resln_kernel<<<BLTOK, 256>>>(h, res, nullptr, hnh, hnl,
                                     normw + lyr * DM, normb + lyr * DM, lyr > 0 ? 1 : 0);
        mma_gemm_a<<<dim3(64, 24), 256, MMASMEM>>>(                       // slot 3 control
            winh + (size_t)lyr * NIN_W, winl + (size_t)lyr * NIN_W, hnh, hnl, xz, DM, BLTOK);
        conv_silu_kernel<<<(DI * BLTOK / 4 + 255) / 256, 256>>>(convw + lyr * DI * 4, convb + lyr * DI);
        sgemm_xproj_splitk<<<dim3(64, 3, XP_KSPL), 256>>>(
            xpW + (long)lyr * XP_M * DI, xconv);
        xproj_reduce_kernel<<<(2 * DS * BLTOK + 255) / 256, 256>>>();
        sgemm_dtproj<<<dim3(64, 24), 256>>>(
            dtW + (long)lyr * DI * DTR, delta, dtb + lyr * DI);
        scanA_kernel<<<SCAN_WARPS / 4, 128>>>(Alog + (long)lyr * DI * DS);
        scanB_kernel<<<SCANB_WARPS / 4, 128>>>();
        scanC_kernel<<<SCAN_WARPS / 4, 128>>>(Alog + (long)lyr * DI * DS, Dv + lyr * DI);
        tcvt_kernel<<<dim3(BLTOK / 32, DI / 32), 256>>>(y, yh, yl);
        mma_gemm_b<<<dim3(64, 6), 256, MMASMEM>>>(
            wouth + (size_t)lyr * NOUT_W, woutl + (size_t)lyr * NOUT_W, yh, yl, h, DI, DM);
    }

    resln_kernel<<<BLTOK, 256>>>(h, res, out, nullptr, nullptr, nfw, nfb, 1);
}